// round 13
// baseline (speedup 1.0000x reference)
#include <cuda_runtime.h>
#include <cuda_bf16.h>
#include <cstdint>

#define NN 50000
#define DD 128
#define EE 800000
#define NBT 391           // ceil(50000/128) GEMM row tiles

typedef unsigned short ushortt;

// ---------------- scratch (device globals) ----------------
__device__ __align__(16) float g_h[NN * DD];
__device__ __align__(16) float g_x[NN * DD];
__device__ __align__(16) __nv_bfloat16 g_xhi[NN * DD];  // combined feat, bf16 hi plane
__device__ __align__(16) __nv_bfloat16 g_xlo[NN * DD];  // combined feat, bf16 lo plane
__device__ float g_sum[DD];
__device__ float g_sumsq[DD];
// CSR
__device__ int g_cnt[NN];
__device__ int g_row[NN + 1];
__device__ int g_cur[NN];
__device__ int g_adj[EE];
// W images, transposed to [n][k] row-major bf16, hi/lo split; 6 mats
__device__ __align__(16) __nv_bfloat16 g_whi[6 * 16384];
__device__ __align__(16) __nv_bfloat16 g_wlo[6 * 16384];

// ---------------- helpers ----------------
__device__ __forceinline__ uint32_t smem_u32(const void* p) {
    uint32_t a;
    asm("{ .reg .u64 t; cvta.to.shared.u64 t, %1; cvt.u32.u64 %0, t; }" : "=r"(a) : "l"(p));
    return a;
}
__device__ __forceinline__ uint32_t pack2bf(__nv_bfloat16 a, __nv_bfloat16 b) {
    return (uint32_t)__bfloat16_as_ushort(a) | ((uint32_t)__bfloat16_as_ushort(b) << 16);
}
__device__ __forceinline__ void ldm_x4(uint32_t addr, uint32_t* r) {
    asm volatile("ldmatrix.sync.aligned.m8n8.x4.shared.b16 {%0,%1,%2,%3}, [%4];"
        : "=r"(r[0]), "=r"(r[1]), "=r"(r[2]), "=r"(r[3]) : "r"(addr));
}
__device__ __forceinline__ void mma_bf16(float* d, const uint32_t* a, const uint32_t* b) {
    asm volatile("mma.sync.aligned.m16n8k16.row.col.f32.bf16.bf16.f32 "
        "{%0,%1,%2,%3}, {%4,%5,%6,%7}, {%8,%9}, {%0,%1,%2,%3};"
        : "+f"(d[0]), "+f"(d[1]), "+f"(d[2]), "+f"(d[3])
        : "r"(a[0]), "r"(a[1]), "r"(a[2]), "r"(a[3]), "r"(b[0]), "r"(b[1]));
}
__device__ __forceinline__ void cp16(uint32_t sm, const void* g) {
    asm volatile("cp.async.ca.shared.global [%0], [%1], 16;" :: "r"(sm), "l"(g));
}
#define CP_COMMIT() asm volatile("cp.async.commit_group;" ::: "memory")
#define CP_WAIT(n)  asm volatile("cp.async.wait_group %0;" :: "n"(n) : "memory")

#define PITCH 40                 // bf16 per smem plane row (80B: conflict-free ldmatrix)
#define PS 10240                 // plane bytes: 128*PITCH*2
// GEMM1 smem: [Xhi|Xlo](single) [Whi|Wlo](buf0) [Whi|Wlo](buf1) -> 60KB, 3 blocks/SM
#define X1_OFF    0
#define W_OFF1(b) (2 * PS + (b) * 2 * PS)
#define SM1_TOT   (6 * PS)       // 61440
// GEMM2 smem: [Xhi|Xlo] [Whi|Wlo](buf0) [Whi|Wlo](buf1) [scale|shift]
#define W_OFF2(b) (2 * PS + (b) * 2 * PS)
#define SC_OFF    (6 * PS)
#define SM2_TOT   (6 * PS + 1024)

// ---------------- CSR build + weight prep ----------------
__global__ void __launch_bounds__(256) k_prep(const float* __restrict__ W1,
                                              const float* __restrict__ W2) {
    if (blockIdx.x < 6) {
        int m = blockIdx.x;
        const float* src = (m < 3) ? (W1 + m * 16384) : (W2 + (m - 3) * 16384);
        __nv_bfloat16* hi = g_whi + m * 16384;
        __nv_bfloat16* lo = g_wlo + m * 16384;
        for (int i = threadIdx.x; i < 16384; i += 256) {
            int k = i >> 7, n = i & 127;
            float v = src[i];
            __nv_bfloat16 h = __float2bfloat16(v);
            __nv_bfloat16 l = __float2bfloat16(v - __bfloat162float(h));
            hi[n * 128 + k] = h;
            lo[n * 128 + k] = l;
        }
    } else {
        int i = (blockIdx.x - 6) * 256 + threadIdx.x;
        if (i < NN) g_cnt[i] = 0;
    }
}
__global__ void k_hist(const int* __restrict__ dst) {
    int e = blockIdx.x * blockDim.x + threadIdx.x;
    if (e < EE) atomicAdd(&g_cnt[dst[e]], 1);
}
__global__ void __launch_bounds__(1024) k_scan() {
    __shared__ int sm[1024];
    const int CH = 49;
    int t = threadIdx.x;
    int beg = t * CH;
    int tot = 0;
    for (int i = beg; i < beg + CH && i < NN; i++) tot += g_cnt[i];
    sm[t] = tot;
    __syncthreads();
    for (int off = 1; off < 1024; off <<= 1) {
        int v = (t >= off) ? sm[t - off] : 0;
        __syncthreads();
        sm[t] += v;
        __syncthreads();
    }
    int base = sm[t] - tot;
    for (int i = beg; i < beg + CH && i < NN; i++) {
        g_row[i] = base; g_cur[i] = 0; base += g_cnt[i];
    }
    if (t == 1023) g_row[NN] = sm[1023];
}
__global__ void k_fill(const int* __restrict__ src, const int* __restrict__ dst) {
    int e = blockIdx.x * blockDim.x + threadIdx.x;
    if (e >= EE) return;
    int d = dst[e];
    int pos = atomicAdd(&g_cur[d], 1);
    g_adj[g_row[d] + pos] = src[e];
}

// ---------------- gather + combine -> bf16 hi/lo planes; zeroes BN stats ----------------
__global__ void k_gather(const float* __restrict__ Xext, int use_ext,
                         const float* __restrict__ epsp) {
    if (blockIdx.x == 0 && threadIdx.x < DD) {
        g_sum[threadIdx.x] = 0.f;
        g_sumsq[threadIdx.x] = 0.f;
    }
    const float* X = use_ext ? Xext : (const float*)g_x;
    int gid = blockIdx.x * blockDim.x + threadIdx.x;
    int node = gid >> 5;
    if (node >= NN) return;
    int lane = gid & 31;
    int beg = g_row[node], end = g_row[node + 1];
    float4 a = make_float4(0.f, 0.f, 0.f, 0.f);
    for (int i = beg; i < end; i++) {
        int s = g_adj[i];
        float4 v = ((const float4*)X)[s * 32 + lane];
        a.x += v.x; a.y += v.y; a.z += v.z; a.w += v.w;
    }
    float4 xv = ((const float4*)X)[node * 32 + lane];
    float pa = a.x * a.x + a.y * a.y + a.z * a.z + a.w * a.w;
    float px = xv.x * xv.x + xv.y * xv.y + xv.z * xv.z + xv.w * xv.w;
    #pragma unroll
    for (int off = 16; off; off >>= 1) {
        pa += __shfl_xor_sync(0xffffffffu, pa, off);
        px += __shfl_xor_sync(0xffffffffu, px, off);
    }
    float ia = 1.f / fmaxf(sqrtf(pa), 1e-12f);
    float ix = (1.f + epsp[0]) / fmaxf(sqrtf(px), 1e-12f);
    float o[4];
    o[0] = a.x * ia + xv.x * ix;
    o[1] = a.y * ia + xv.y * ix;
    o[2] = a.z * ia + xv.z * ix;
    o[3] = a.w * ia + xv.w * ix;
    __nv_bfloat16 h[4], l[4];
    #pragma unroll
    for (int j = 0; j < 4; j++) {
        h[j] = __float2bfloat16(o[j]);
        l[j] = __float2bfloat16(o[j] - __bfloat162float(h[j]));
    }
    *(uint2*)(g_xhi + node * DD + lane * 4) = make_uint2(pack2bf(h[0], h[1]), pack2bf(h[2], h[3]));
    *(uint2*)(g_xlo + node * DD + lane * 4) = make_uint2(pack2bf(l[0], l[1]), pack2bf(l[2], l[3]));
}

// ---------------- shared GEMM machinery (frag maps validated R8-R11) ----------------
__device__ __forceinline__ void prefetch_w(char* sm, uint32_t woff, int mat, int ck) {
    int tid = threadIdx.x;
    const __nv_bfloat16* gh = g_whi + mat * 16384 + ck * 32;
    const __nv_bfloat16* gl = g_wlo + mat * 16384 + ck * 32;
    uint32_t sh = smem_u32(sm + woff);
    uint32_t sl = sh + PS;
    for (int i = tid; i < 512; i += 256) {
        int row = i >> 2, q = i & 3;
        uint32_t so = (uint32_t)(row * PITCH + q * 8) * 2;
        cp16(sh + so, gh + row * 128 + q * 8);
        cp16(sl + so, gl + row * 128 + q * 8);
    }
}

__device__ __forceinline__ void prefetch_x_guarded(char* sm, uint32_t xoff, int row0, int ck) {
    int tid = threadIdx.x;
    uint32_t sh = smem_u32(sm + xoff);
    for (int i = tid; i < 512; i += 256) {
        int row = i >> 2, q = i & 3;
        int gr = row0 + row;
        uint32_t so = (uint32_t)(row * PITCH + q * 8) * 2;
        if (gr < NN) {
            cp16(sh + so, g_xhi + gr * DD + ck * 32 + q * 8);
            cp16(sh + PS + so, g_xlo + gr * DD + ck * 32 + q * 8);
        } else {
            uint4 z = make_uint4(0, 0, 0, 0);
            *(uint4*)(sm + xoff + so) = z;
            *(uint4*)(sm + xoff + PS + so) = z;
        }
    }
}

// A loaded once, multiplied by both W planes (hi+lo)
__device__ __forceinline__ void do_pass2(uint32_t abase, uint32_t bwh, uint32_t bwl,
                                         int wm, int wn, int lane, float acc[4][4][4]) {
    #pragma unroll
    for (int ks = 0; ks < 2; ks++) {
        uint32_t af[4][4];
        #pragma unroll
        for (int mt = 0; mt < 4; mt++) {
            int row = wm * 64 + mt * 16 + (lane & 7) + ((lane >> 3) & 1) * 8;
            int col = ks * 16 + ((lane >> 4) & 1) * 8;
            ldm_x4(abase + (row * PITCH + col) * 2, af[mt]);
        }
        uint32_t bh[4][2], bl[4][2];
        #pragma unroll
        for (int jp = 0; jp < 2; jp++) {
            int n = wn * 32 + jp * 16 + ((lane >> 4) & 1) * 8 + (lane & 7);
            int col = ks * 16 + ((lane >> 3) & 1) * 8;
            uint32_t r4[4];
            ldm_x4(bwh + (n * PITCH + col) * 2, r4);
            bh[jp * 2][0] = r4[0]; bh[jp * 2][1] = r4[1];
            bh[jp * 2 + 1][0] = r4[2]; bh[jp * 2 + 1][1] = r4[3];
            ldm_x4(bwl + (n * PITCH + col) * 2, r4);
            bl[jp * 2][0] = r4[0]; bl[jp * 2][1] = r4[1];
            bl[jp * 2 + 1][0] = r4[2]; bl[jp * 2 + 1][1] = r4[3];
        }
        #pragma unroll
        for (int mt = 0; mt < 4; mt++)
            #pragma unroll
            for (int nt = 0; nt < 4; nt++) {
                mma_bf16(acc[mt][nt], af[mt], bh[nt]);
                mma_bf16(acc[mt][nt], af[mt], bl[nt]);
            }
    }
}

// single pass: Xlo against W-hi
__device__ __forceinline__ void do_pass1(uint32_t abase, uint32_t bwh,
                                         int wm, int wn, int lane, float acc[4][4][4]) {
    #pragma unroll
    for (int ks = 0; ks < 2; ks++) {
        uint32_t af[4][4];
        #pragma unroll
        for (int mt = 0; mt < 4; mt++) {
            int row = wm * 64 + mt * 16 + (lane & 7) + ((lane >> 3) & 1) * 8;
            int col = ks * 16 + ((lane >> 4) & 1) * 8;
            ldm_x4(abase + (row * PITCH + col) * 2, af[mt]);
        }
        uint32_t bf[4][2];
        #pragma unroll
        for (int jp = 0; jp < 2; jp++) {
            int n = wn * 32 + jp * 16 + ((lane >> 4) & 1) * 8 + (lane & 7);
            int col = ks * 16 + ((lane >> 3) & 1) * 8;
            uint32_t r4[4];
            ldm_x4(bwh + (n * PITCH + col) * 2, r4);
            bf[jp * 2][0] = r4[0]; bf[jp * 2][1] = r4[1];
            bf[jp * 2 + 1][0] = r4[2]; bf[jp * 2 + 1][1] = r4[3];
        }
        #pragma unroll
        for (int mt = 0; mt < 4; mt++)
            #pragma unroll
            for (int nt = 0; nt < 4; nt++)
                mma_bf16(acc[mt][nt], af[mt], bf[nt]);
    }
}

extern __shared__ __align__(16) char dsm[];

// ---------------- GEMM1: h = comb @ W1 + b1 -> g_h, BN stats via atomics ----------------
// X hi/lo single-buffered + W double-buffered (split commit groups); 3 blocks/SM, 1 wave
__global__ void __launch_bounds__(256, 3) k_gemm1_p(int mat, const float* __restrict__ b) {
    char* sm = dsm;
    int tid = threadIdx.x;
    int wid = tid >> 5, lane = tid & 31;
    int wm = wid & 1, wn = wid >> 1;
    int row0 = blockIdx.x * 128;

    float acc[4][4][4];
    #pragma unroll
    for (int mt = 0; mt < 4; mt++)
        #pragma unroll
        for (int nt = 0; nt < 4; nt++)
            #pragma unroll
            for (int i = 0; i < 4; i++) acc[mt][nt][i] = 0.f;

    // preload: X0 (group), W0 (group)
    prefetch_x_guarded(sm, X1_OFF, row0, 0);
    CP_COMMIT();
    prefetch_w(sm, W_OFF1(0), mat, 0);
    CP_COMMIT();

    int buf = 0;
    for (int ck = 0; ck < 4; ck++) {
        if (ck > 0) {
            __syncthreads();                       // everyone done reading X(ck-1)
            prefetch_x_guarded(sm, X1_OFF, row0, ck);
            CP_COMMIT();
        }
        if (ck < 3) {
            prefetch_w(sm, W_OFF1(buf ^ 1), mat, ck + 1);
            CP_COMMIT();
            CP_WAIT(1);                            // X(ck) + W(ck) done; W(ck+1) in flight
        } else {
            CP_WAIT(0);
        }
        __syncthreads();
        uint32_t axh = smem_u32(sm + X1_OFF);
        uint32_t axl = axh + PS;
        uint32_t bwh = smem_u32(sm + W_OFF1(buf));
        do_pass2(axh, bwh, bwh + PS, wm, wn, lane, acc);  // Xhi*(Whi+Wlo)
        do_pass1(axl, bwh, wm, wn, lane, acc);            // Xlo*Whi
        buf ^= 1;
    }

    // epilogue: bias, store h, BN partials -> global atomics (validated)
    float ls[4][2], lq[4][2];
    #pragma unroll
    for (int nt = 0; nt < 4; nt++) { ls[nt][0] = ls[nt][1] = lq[nt][0] = lq[nt][1] = 0.f; }
    #pragma unroll
    for (int mt = 0; mt < 4; mt++) {
        int r0 = row0 + wm * 64 + mt * 16 + (lane >> 2);
        int r1 = r0 + 8;
        #pragma unroll
        for (int nt = 0; nt < 4; nt++) {
            int c = wn * 32 + nt * 8 + (lane & 3) * 2;
            float b0 = b[c], b1 = b[c + 1];
            float v0 = acc[mt][nt][0] + b0, v1 = acc[mt][nt][1] + b1;
            float v2 = acc[mt][nt][2] + b0, v3 = acc[mt][nt][3] + b1;
            if (r0 < NN) {
                *(float2*)(g_h + r0 * DD + c) = make_float2(v0, v1);
                ls[nt][0] += v0; ls[nt][1] += v1;
                lq[nt][0] += v0 * v0; lq[nt][1] += v1 * v1;
            }
            if (r1 < NN) {
                *(float2*)(g_h + r1 * DD + c) = make_float2(v2, v3);
                ls[nt][0] += v2; ls[nt][1] += v3;
                lq[nt][0] += v2 * v2; lq[nt][1] += v3 * v3;
            }
        }
    }
    #pragma unroll
    for (int off = 4; off <= 16; off <<= 1) {
        #pragma unroll
        for (int nt = 0; nt < 4; nt++) {
            ls[nt][0] += __shfl_xor_sync(0xffffffffu, ls[nt][0], off);
            ls[nt][1] += __shfl_xor_sync(0xffffffffu, ls[nt][1], off);
            lq[nt][0] += __shfl_xor_sync(0xffffffffu, lq[nt][0], off);
            lq[nt][1] += __shfl_xor_sync(0xffffffffu, lq[nt][1], off);
        }
    }
    __syncthreads();
    float* ssum = (float*)sm;
    float* ssq  = ssum + 256;
    if (lane < 4) {
        #pragma unroll
        for (int nt = 0; nt < 4; nt++) {
            ssum[wid * 32 + nt * 8 + lane * 2]     = ls[nt][0];
            ssum[wid * 32 + nt * 8 + lane * 2 + 1] = ls[nt][1];
            ssq[wid * 32 + nt * 8 + lane * 2]      = lq[nt][0];
            ssq[wid * 32 + nt * 8 + lane * 2 + 1]  = lq[nt][1];
        }
    }
    __syncthreads();
    if (tid < DD) {
        int w0 = (tid >> 5) * 2;
        float s = ssum[w0 * 32 + (tid & 31)] + ssum[(w0 + 1) * 32 + (tid & 31)];
        float q = ssq[w0 * 32 + (tid & 31)] + ssq[(w0 + 1) * 32 + (tid & 31)];
        atomicAdd(&g_sum[tid], s);
        atomicAdd(&g_sumsq[tid], q);
    }
}

// ---------------- GEMM2: out = relu?(bn_relu(h) @ W2 + b2); BN finalize inline ----------------
__global__ void __launch_bounds__(256, 3) k_gemm2_p(int mat, const float* __restrict__ gamma,
                                                    const float* __restrict__ beta,
                                                    const float* __restrict__ b,
                                                    float* __restrict__ OutExt,
                                                    int internal, int do_relu) {
    char* sm = dsm;
    float* Out = internal ? (float*)g_x : OutExt;
    int tid = threadIdx.x;
    int wid = tid >> 5, lane = tid & 31;
    int wm = wid & 1, wn = wid >> 1;
    int row0 = blockIdx.x * 128;

    float acc[4][4][4];
    #pragma unroll
    for (int mt = 0; mt < 4; mt++)
        #pragma unroll
        for (int nt = 0; nt < 4; nt++)
            #pragma unroll
            for (int i = 0; i < 4; i++) acc[mt][nt][i] = 0.f;

    prefetch_w(sm, W_OFF2(0), mat, 0);
    CP_COMMIT();

    // inline BN finalize: scale/shift into smem (overlaps W prefetch)
    float* sscale = (float*)(sm + SC_OFF);
    float* sshift = sscale + DD;
    if (tid < DD) {
        float mean = g_sum[tid] * (1.f / NN);
        float var  = g_sumsq[tid] * (1.f / NN) - mean * mean;
        float sc = gamma[tid] * rsqrtf(var + 1e-5f);
        sscale[tid] = sc;
        sshift[tid] = beta[tid] - mean * sc;
    }

    ushortt* xhi = (ushortt*)sm;
    ushortt* xlo = (ushortt*)(sm + PS);
    int buf = 0;
    for (int ck = 0; ck < 4; ck++) {
        __syncthreads();   // prev passes done; also publishes sscale/sshift at ck=0
        if (ck < 3) {
            prefetch_w(sm, W_OFF2(buf ^ 1), mat, ck + 1);
            CP_COMMIT();
        }
        // convert X chunk hi+lo (overlaps W cp.async)
        {
            int r = tid >> 1, half = tid & 1;
            int gr = row0 + r;
            int gc = ck * 32 + half * 16;
            uint4 hv = make_uint4(0, 0, 0, 0), lv = make_uint4(0, 0, 0, 0);
            uint4 hv2 = hv, lv2 = lv;
            if (gr < NN) {
                const float* srcp = g_h + gr * DD + gc;
                uint32_t hp[8], lp[8];
                #pragma unroll
                for (int i = 0; i < 8; i++) {
                    float v0 = fmaxf(fmaf(srcp[2 * i], sscale[gc + 2 * i], sshift[gc + 2 * i]), 0.f);
                    float v1 = fmaxf(fmaf(srcp[2 * i + 1], sscale[gc + 2 * i + 1], sshift[gc + 2 * i + 1]), 0.f);
                    __nv_bfloat16 h0 = __float2bfloat16(v0), h1 = __float2bfloat16(v1);
                    __nv_bfloat16 l0 = __float2bfloat16(v0 - __bfloat162float(h0));
                    __nv_bfloat16 l1 = __float2bfloat16(v1 - __bfloat162float(h1));
                    hp[i] = pack2bf(h0, h1);
                    lp[i] = pack2bf(l0, l1);
                }
                hv = make_uint4(hp[0], hp[1], hp[2], hp[3]);
                hv2 = make_uint4(hp[4], hp[5], hp[6], hp[7]);
                lv = make_uint4(lp[0], lp[1], lp[2], lp[3]);
                lv2 = make_uint4(lp[4], lp[5], lp[6], lp[7]);
            }
            *(uint4*)(xhi + r * PITCH + half * 16)     = hv;
            *(uint4*)(xhi + r * PITCH + half * 16 + 8) = hv2;
            *(uint4*)(xlo + r * PITCH + half * 16)     = lv;
            *(uint4*)(xlo + r * PITCH + half * 16 + 8) = lv2;
        }
        if (ck < 3) CP_WAIT(1); else CP_WAIT(0);
        __syncthreads();
        uint32_t axh = smem_u32(xhi);
        uint32_t axl = smem_u32(xlo);
        uint32_t bwh = smem_u32(sm + W_OFF2(buf));
        do_pass2(axh, bwh, bwh + PS, wm, wn, lane, acc);
        do_pass1(axl, bwh, wm, wn, lane, acc);
        buf ^= 1;
    }

    #pragma unroll
    for (int mt = 0; mt < 4; mt++) {
        int r0 = row0 + wm * 64 + mt * 16 + (lane >> 2);
        int r1 = r0 + 8;
        #pragma unroll
        for (int nt = 0; nt < 4; nt++) {
            int c = wn * 32 + nt * 8 + (lane & 3) * 2;
            float b0 = b[c], b1 = b[c + 1];
            float v0 = acc[mt][nt][0] + b0, v1 = acc[mt][nt][1] + b1;
            float v2 = acc[mt][nt][2] + b0, v3 = acc[mt][nt][3] + b1;
            if (do_relu) {
                v0 = fmaxf(v0, 0.f); v1 = fmaxf(v1, 0.f);
                v2 = fmaxf(v2, 0.f); v3 = fmaxf(v3, 0.f);
            }
            if (r0 < NN) *(float2*)(Out + r0 * DD + c) = make_float2(v0, v1);
            if (r1 < NN) *(float2*)(Out + r1 * DD + c) = make_float2(v2, v3);
        }
    }
}

extern "C" void kernel_launch(void* const* d_in, const int* in_sizes, int n_in,
                              void* d_out, int out_size) {
    (void)in_sizes; (void)n_in; (void)out_size;
    const float* x     = (const float*)d_in[0];
    const int*   ei    = (const int*)d_in[1];   // int32 (JAX x64 disabled)
    const float* W1    = (const float*)d_in[2];
    const float* b1    = (const float*)d_in[3];
    const float* gamma = (const float*)d_in[4];
    const float* beta  = (const float*)d_in[5];
    const float* W2    = (const float*)d_in[6];
    const float* b2    = (const float*)d_in[7];
    const float* eps   = (const float*)d_in[8];
    float* out = (float*)d_out;

    const int* src = ei;
    const int* dst = ei + EE;

    cudaFuncSetAttribute(k_gemm1_p, cudaFuncAttributeMaxDynamicSharedMemorySize, SM1_TOT);
    cudaFuncSetAttribute(k_gemm2_p, cudaFuncAttributeMaxDynamicSharedMemorySize, SM2_TOT);

    k_prep<<<6 + (NN + 255) / 256, 256>>>(W1, W2);
    k_hist<<<(EE + 255) / 256, 256>>>(dst);
    k_scan<<<1, 1024>>>();
    k_fill<<<(EE + 255) / 256, 256>>>(src, dst);

    for (int l = 0; l < 3; l++) {
        int use_ext = (l == 0) ? 1 : 0;
        int internal = (l == 2) ? 0 : 1;
        k_gather<<<(NN * 32 + 255) / 256, 256>>>(x, use_ext, eps + l);
        k_gemm1_p<<<NBT, 256, SM1_TOT>>>(l, b1 + l * DD);
        k_gemm2_p<<<NBT, 256, SM2_TOT>>>(3 + l, gamma + l * DD, beta + l * DD,
                                         b2 + l * DD, out, internal, (l < 2) ? 1 : 0);
    }
}

// round 14
// speedup vs baseline: 1.2306x; 1.2306x over previous
#include <cuda_runtime.h>
#include <cuda_bf16.h>
#include <cstdint>

#define NN 50000
#define DD 128
#define EE 800000
#define NBT 391           // ceil(50000/128) GEMM row tiles

typedef unsigned short ushortt;

// ---------------- scratch (device globals) ----------------
__device__ __align__(16) float g_h[NN * DD];
__device__ __align__(16) float g_x[NN * DD];
__device__ __align__(16) __nv_bfloat16 g_xhi[NN * DD];  // combined feat, bf16 hi plane
__device__ __align__(16) __nv_bfloat16 g_xlo[NN * DD];  // combined feat, bf16 lo plane
__device__ float g_sum[DD];
__device__ float g_sumsq[DD];
// CSR
__device__ int g_cnt[NN];
__device__ int g_row[NN + 1];
__device__ int g_cur[NN];
__device__ int g_adj[EE];
// W images, transposed to [n][k] row-major bf16, hi/lo split; 6 mats
__device__ __align__(16) __nv_bfloat16 g_whi[6 * 16384];
__device__ __align__(16) __nv_bfloat16 g_wlo[6 * 16384];

// ---------------- helpers ----------------
__device__ __forceinline__ uint32_t smem_u32(const void* p) {
    uint32_t a;
    asm("{ .reg .u64 t; cvta.to.shared.u64 t, %1; cvt.u32.u64 %0, t; }" : "=r"(a) : "l"(p));
    return a;
}
__device__ __forceinline__ uint32_t pack2bf(__nv_bfloat16 a, __nv_bfloat16 b) {
    return (uint32_t)__bfloat16_as_ushort(a) | ((uint32_t)__bfloat16_as_ushort(b) << 16);
}
__device__ __forceinline__ void ldm_x4(uint32_t addr, uint32_t* r) {
    asm volatile("ldmatrix.sync.aligned.m8n8.x4.shared.b16 {%0,%1,%2,%3}, [%4];"
        : "=r"(r[0]), "=r"(r[1]), "=r"(r[2]), "=r"(r[3]) : "r"(addr));
}
__device__ __forceinline__ void mma_bf16(float* d, const uint32_t* a, const uint32_t* b) {
    asm volatile("mma.sync.aligned.m16n8k16.row.col.f32.bf16.bf16.f32 "
        "{%0,%1,%2,%3}, {%4,%5,%6,%7}, {%8,%9}, {%0,%1,%2,%3};"
        : "+f"(d[0]), "+f"(d[1]), "+f"(d[2]), "+f"(d[3])
        : "r"(a[0]), "r"(a[1]), "r"(a[2]), "r"(a[3]), "r"(b[0]), "r"(b[1]));
}
__device__ __forceinline__ void cp16(uint32_t sm, const void* g) {
    asm volatile("cp.async.ca.shared.global [%0], [%1], 16;" :: "r"(sm), "l"(g));
}
#define CP_COMMIT() asm volatile("cp.async.commit_group;" ::: "memory")
#define CP_WAIT(n)  asm volatile("cp.async.wait_group %0;" :: "n"(n) : "memory")

#define PITCH 40                 // bf16 per smem plane row (80B: conflict-free ldmatrix)
#define PS 10240                 // plane bytes: 128*PITCH*2
// GEMM1 smem: [Xhi|Xlo](buf0) [Xhi|Xlo](buf1) [Whi|Wlo](buf0) [Whi|Wlo](buf1)
#define X_OFF(b)  ((b) * 2 * PS)
#define W_OFF1(b) (4 * PS + (b) * 2 * PS)
#define SM1_TOT   (8 * PS)       // 81920
// GEMM2 smem: [Xhi|Xlo] [Whi|Wlo](buf0) [Whi|Wlo](buf1) [scale|shift]
#define W_OFF2(b) (2 * PS + (b) * 2 * PS)
#define SC_OFF    (6 * PS)
#define SM2_TOT   (6 * PS + 1024)

// ---------------- CSR build + weight prep ----------------
__global__ void __launch_bounds__(256) k_prep(const float* __restrict__ W1,
                                              const float* __restrict__ W2) {
    if (blockIdx.x < 6) {
        int m = blockIdx.x;
        const float* src = (m < 3) ? (W1 + m * 16384) : (W2 + (m - 3) * 16384);
        __nv_bfloat16* hi = g_whi + m * 16384;
        __nv_bfloat16* lo = g_wlo + m * 16384;
        for (int i = threadIdx.x; i < 16384; i += 256) {
            int k = i >> 7, n = i & 127;
            float v = src[i];
            __nv_bfloat16 h = __float2bfloat16(v);
            __nv_bfloat16 l = __float2bfloat16(v - __bfloat162float(h));
            hi[n * 128 + k] = h;
            lo[n * 128 + k] = l;
        }
    } else {
        int i = (blockIdx.x - 6) * 256 + threadIdx.x;
        if (i < NN) g_cnt[i] = 0;
    }
}
__global__ void k_hist(const int* __restrict__ dst) {
    int e = blockIdx.x * blockDim.x + threadIdx.x;
    if (e < EE) atomicAdd(&g_cnt[dst[e]], 1);
}
__global__ void __launch_bounds__(1024) k_scan() {
    __shared__ int sm[1024];
    const int CH = 49;
    int t = threadIdx.x;
    int beg = t * CH;
    int tot = 0;
    for (int i = beg; i < beg + CH && i < NN; i++) tot += g_cnt[i];
    sm[t] = tot;
    __syncthreads();
    for (int off = 1; off < 1024; off <<= 1) {
        int v = (t >= off) ? sm[t - off] : 0;
        __syncthreads();
        sm[t] += v;
        __syncthreads();
    }
    int base = sm[t] - tot;
    for (int i = beg; i < beg + CH && i < NN; i++) {
        g_row[i] = base; g_cur[i] = 0; base += g_cnt[i];
    }
    if (t == 1023) g_row[NN] = sm[1023];
}
__global__ void k_fill(const int* __restrict__ src, const int* __restrict__ dst) {
    int e = blockIdx.x * blockDim.x + threadIdx.x;
    if (e >= EE) return;
    int d = dst[e];
    int pos = atomicAdd(&g_cur[d], 1);
    g_adj[g_row[d] + pos] = src[e];
}

// ---------------- gather + combine -> bf16 hi/lo planes; zeroes BN stats ----------------
__global__ void k_gather(const float* __restrict__ Xext, int use_ext,
                         const float* __restrict__ epsp) {
    if (blockIdx.x == 0 && threadIdx.x < DD) {
        g_sum[threadIdx.x] = 0.f;
        g_sumsq[threadIdx.x] = 0.f;
    }
    const float* X = use_ext ? Xext : (const float*)g_x;
    int gid = blockIdx.x * blockDim.x + threadIdx.x;
    int node = gid >> 5;
    if (node >= NN) return;
    int lane = gid & 31;
    int beg = g_row[node], end = g_row[node + 1];
    float4 a = make_float4(0.f, 0.f, 0.f, 0.f);
    for (int i = beg; i < end; i++) {
        int s = g_adj[i];
        float4 v = ((const float4*)X)[s * 32 + lane];
        a.x += v.x; a.y += v.y; a.z += v.z; a.w += v.w;
    }
    float4 xv = ((const float4*)X)[node * 32 + lane];
    float pa = a.x * a.x + a.y * a.y + a.z * a.z + a.w * a.w;
    float px = xv.x * xv.x + xv.y * xv.y + xv.z * xv.z + xv.w * xv.w;
    #pragma unroll
    for (int off = 16; off; off >>= 1) {
        pa += __shfl_xor_sync(0xffffffffu, pa, off);
        px += __shfl_xor_sync(0xffffffffu, px, off);
    }
    float ia = 1.f / fmaxf(sqrtf(pa), 1e-12f);
    float ix = (1.f + epsp[0]) / fmaxf(sqrtf(px), 1e-12f);
    float o[4];
    o[0] = a.x * ia + xv.x * ix;
    o[1] = a.y * ia + xv.y * ix;
    o[2] = a.z * ia + xv.z * ix;
    o[3] = a.w * ia + xv.w * ix;
    __nv_bfloat16 h[4], l[4];
    #pragma unroll
    for (int j = 0; j < 4; j++) {
        h[j] = __float2bfloat16(o[j]);
        l[j] = __float2bfloat16(o[j] - __bfloat162float(h[j]));
    }
    *(uint2*)(g_xhi + node * DD + lane * 4) = make_uint2(pack2bf(h[0], h[1]), pack2bf(h[2], h[3]));
    *(uint2*)(g_xlo + node * DD + lane * 4) = make_uint2(pack2bf(l[0], l[1]), pack2bf(l[2], l[3]));
}

// ---------------- shared GEMM machinery (frag maps validated R8-R13) ----------------
__device__ __forceinline__ void prefetch_w(char* sm, uint32_t woff, int mat, int ck) {
    int tid = threadIdx.x;
    const __nv_bfloat16* gh = g_whi + mat * 16384 + ck * 32;
    const __nv_bfloat16* gl = g_wlo + mat * 16384 + ck * 32;
    uint32_t sh = smem_u32(sm + woff);
    uint32_t sl = sh + PS;
    for (int i = tid; i < 512; i += 256) {
        int row = i >> 2, q = i & 3;
        uint32_t so = (uint32_t)(row * PITCH + q * 8) * 2;
        cp16(sh + so, gh + row * 128 + q * 8);
        cp16(sl + so, gl + row * 128 + q * 8);
    }
}

__device__ __forceinline__ void prefetch_x_guarded(char* sm, uint32_t xoff, int row0, int ck) {
    int tid = threadIdx.x;
    uint32_t sh = smem_u32(sm + xoff);
    for (int i = tid; i < 512; i += 256) {
        int row = i >> 2, q = i & 3;
        int gr = row0 + row;
        uint32_t so = (uint32_t)(row * PITCH + q * 8) * 2;
        if (gr < NN) {
            cp16(sh + so, g_xhi + gr * DD + ck * 32 + q * 8);
            cp16(sh + PS + so, g_xlo + gr * DD + ck * 32 + q * 8);
        } else {
            uint4 z = make_uint4(0, 0, 0, 0);
            *(uint4*)(sm + xoff + so) = z;
            *(uint4*)(sm + xoff + PS + so) = z;
        }
    }
}

// A loaded once, multiplied by both W planes (hi+lo)  [numerics validated R13]
__device__ __forceinline__ void do_pass2(uint32_t abase, uint32_t bwh, uint32_t bwl,
                                         int wm, int wn, int lane, float acc[4][4][4]) {
    #pragma unroll
    for (int ks = 0; ks < 2; ks++) {
        uint32_t af[4][4];
        #pragma unroll
        for (int mt = 0; mt < 4; mt++) {
            int row = wm * 64 + mt * 16 + (lane & 7) + ((lane >> 3) & 1) * 8;
            int col = ks * 16 + ((lane >> 4) & 1) * 8;
            ldm_x4(abase + (row * PITCH + col) * 2, af[mt]);
        }
        uint32_t bh[4][2], bl[4][2];
        #pragma unroll
        for (int jp = 0; jp < 2; jp++) {
            int n = wn * 32 + jp * 16 + ((lane >> 4) & 1) * 8 + (lane & 7);
            int col = ks * 16 + ((lane >> 3) & 1) * 8;
            uint32_t r4[4];
            ldm_x4(bwh + (n * PITCH + col) * 2, r4);
            bh[jp * 2][0] = r4[0]; bh[jp * 2][1] = r4[1];
            bh[jp * 2 + 1][0] = r4[2]; bh[jp * 2 + 1][1] = r4[3];
            ldm_x4(bwl + (n * PITCH + col) * 2, r4);
            bl[jp * 2][0] = r4[0]; bl[jp * 2][1] = r4[1];
            bl[jp * 2 + 1][0] = r4[2]; bl[jp * 2 + 1][1] = r4[3];
        }
        #pragma unroll
        for (int mt = 0; mt < 4; mt++)
            #pragma unroll
            for (int nt = 0; nt < 4; nt++) {
                mma_bf16(acc[mt][nt], af[mt], bh[nt]);
                mma_bf16(acc[mt][nt], af[mt], bl[nt]);
            }
    }
}

// single pass: Xlo against W-hi
__device__ __forceinline__ void do_pass1(uint32_t abase, uint32_t bwh,
                                         int wm, int wn, int lane, float acc[4][4][4]) {
    #pragma unroll
    for (int ks = 0; ks < 2; ks++) {
        uint32_t af[4][4];
        #pragma unroll
        for (int mt = 0; mt < 4; mt++) {
            int row = wm * 64 + mt * 16 + (lane & 7) + ((lane >> 3) & 1) * 8;
            int col = ks * 16 + ((lane >> 4) & 1) * 8;
            ldm_x4(abase + (row * PITCH + col) * 2, af[mt]);
        }
        uint32_t bf[4][2];
        #pragma unroll
        for (int jp = 0; jp < 2; jp++) {
            int n = wn * 32 + jp * 16 + ((lane >> 4) & 1) * 8 + (lane & 7);
            int col = ks * 16 + ((lane >> 3) & 1) * 8;
            uint32_t r4[4];
            ldm_x4(bwh + (n * PITCH + col) * 2, r4);
            bf[jp * 2][0] = r4[0]; bf[jp * 2][1] = r4[1];
            bf[jp * 2 + 1][0] = r4[2]; bf[jp * 2 + 1][1] = r4[3];
        }
        #pragma unroll
        for (int mt = 0; mt < 4; mt++)
            #pragma unroll
            for (int nt = 0; nt < 4; nt++)
                mma_bf16(acc[mt][nt], af[mt], bf[nt]);
    }
}

extern __shared__ __align__(16) char dsm[];

// ---------------- GEMM1: h = comb @ W1 + b1 -> g_h, BN stats via atomics ----------------
// R11 configuration: X+W both double-buffered, no occupancy clamp
__global__ void __launch_bounds__(256) k_gemm1_p(int mat, const float* __restrict__ b) {
    char* sm = dsm;
    int tid = threadIdx.x;
    int wid = tid >> 5, lane = tid & 31;
    int wm = wid & 1, wn = wid >> 1;
    int row0 = blockIdx.x * 128;

    float acc[4][4][4];
    #pragma unroll
    for (int mt = 0; mt < 4; mt++)
        #pragma unroll
        for (int nt = 0; nt < 4; nt++)
            #pragma unroll
            for (int i = 0; i < 4; i++) acc[mt][nt][i] = 0.f;

    prefetch_x_guarded(sm, X_OFF(0), row0, 0);
    prefetch_w(sm, W_OFF1(0), mat, 0);
    CP_COMMIT();

    int buf = 0;
    for (int ck = 0; ck < 4; ck++) {
        __syncthreads();
        if (ck < 3) {
            prefetch_x_guarded(sm, X_OFF(buf ^ 1), row0, ck + 1);
            prefetch_w(sm, W_OFF1(buf ^ 1), mat, ck + 1);
            CP_COMMIT();
            CP_WAIT(1);
        } else {
            CP_WAIT(0);
        }
        __syncthreads();
        uint32_t axh = smem_u32(sm + X_OFF(buf));
        uint32_t axl = axh + PS;
        uint32_t bwh = smem_u32(sm + W_OFF1(buf));
        do_pass2(axh, bwh, bwh + PS, wm, wn, lane, acc);  // Xhi*(Whi+Wlo), A loaded once
        do_pass1(axl, bwh, wm, wn, lane, acc);            // Xlo*Whi
        buf ^= 1;
    }

    // epilogue: bias, store h, BN partials -> global atomics (validated)
    float ls[4][2], lq[4][2];
    #pragma unroll
    for (int nt = 0; nt < 4; nt++) { ls[nt][0] = ls[nt][1] = lq[nt][0] = lq[nt][1] = 0.f; }
    #pragma unroll
    for (int mt = 0; mt < 4; mt++) {
        int r0 = row0 + wm * 64 + mt * 16 + (lane >> 2);
        int r1 = r0 + 8;
        #pragma unroll
        for (int nt = 0; nt < 4; nt++) {
            int c = wn * 32 + nt * 8 + (lane & 3) * 2;
            float b0 = b[c], b1 = b[c + 1];
            float v0 = acc[mt][nt][0] + b0, v1 = acc[mt][nt][1] + b1;
            float v2 = acc[mt][nt][2] + b0, v3 = acc[mt][nt][3] + b1;
            if (r0 < NN) {
                *(float2*)(g_h + r0 * DD + c) = make_float2(v0, v1);
                ls[nt][0] += v0; ls[nt][1] += v1;
                lq[nt][0] += v0 * v0; lq[nt][1] += v1 * v1;
            }
            if (r1 < NN) {
                *(float2*)(g_h + r1 * DD + c) = make_float2(v2, v3);
                ls[nt][0] += v2; ls[nt][1] += v3;
                lq[nt][0] += v2 * v2; lq[nt][1] += v3 * v3;
            }
        }
    }
    #pragma unroll
    for (int off = 4; off <= 16; off <<= 1) {
        #pragma unroll
        for (int nt = 0; nt < 4; nt++) {
            ls[nt][0] += __shfl_xor_sync(0xffffffffu, ls[nt][0], off);
            ls[nt][1] += __shfl_xor_sync(0xffffffffu, ls[nt][1], off);
            lq[nt][0] += __shfl_xor_sync(0xffffffffu, lq[nt][0], off);
            lq[nt][1] += __shfl_xor_sync(0xffffffffu, lq[nt][1], off);
        }
    }
    __syncthreads();
    float* ssum = (float*)sm;
    float* ssq  = ssum + 256;
    if (lane < 4) {
        #pragma unroll
        for (int nt = 0; nt < 4; nt++) {
            ssum[wid * 32 + nt * 8 + lane * 2]     = ls[nt][0];
            ssum[wid * 32 + nt * 8 + lane * 2 + 1] = ls[nt][1];
            ssq[wid * 32 + nt * 8 + lane * 2]      = lq[nt][0];
            ssq[wid * 32 + nt * 8 + lane * 2 + 1]  = lq[nt][1];
        }
    }
    __syncthreads();
    if (tid < DD) {
        int w0 = (tid >> 5) * 2;
        float s = ssum[w0 * 32 + (tid & 31)] + ssum[(w0 + 1) * 32 + (tid & 31)];
        float q = ssq[w0 * 32 + (tid & 31)] + ssq[(w0 + 1) * 32 + (tid & 31)];
        atomicAdd(&g_sum[tid], s);
        atomicAdd(&g_sumsq[tid], q);
    }
}

// ---------------- GEMM2: out = relu?(bn_relu(h) @ W2 + b2); BN finalize inline ----------------
__global__ void __launch_bounds__(256) k_gemm2_p(int mat, const float* __restrict__ gamma,
                                                 const float* __restrict__ beta,
                                                 const float* __restrict__ b,
                                                 float* __restrict__ OutExt,
                                                 int internal, int do_relu) {
    char* sm = dsm;
    float* Out = internal ? (float*)g_x : OutExt;
    int tid = threadIdx.x;
    int wid = tid >> 5, lane = tid & 31;
    int wm = wid & 1, wn = wid >> 1;
    int row0 = blockIdx.x * 128;

    float acc[4][4][4];
    #pragma unroll
    for (int mt = 0; mt < 4; mt++)
        #pragma unroll
        for (int nt = 0; nt < 4; nt++)
            #pragma unroll
            for (int i = 0; i < 4; i++) acc[mt][nt][i] = 0.f;

    prefetch_w(sm, W_OFF2(0), mat, 0);
    CP_COMMIT();

    // inline BN finalize: scale/shift into smem (overlaps W prefetch)
    float* sscale = (float*)(sm + SC_OFF);
    float* sshift = sscale + DD;
    if (tid < DD) {
        float mean = g_sum[tid] * (1.f / NN);
        float var  = g_sumsq[tid] * (1.f / NN) - mean * mean;
        float sc = gamma[tid] * rsqrtf(var + 1e-5f);
        sscale[tid] = sc;
        sshift[tid] = beta[tid] - mean * sc;
    }

    ushortt* xhi = (ushortt*)sm;
    ushortt* xlo = (ushortt*)(sm + PS);
    int buf = 0;
    for (int ck = 0; ck < 4; ck++) {
        __syncthreads();   // prev passes done; also publishes sscale/sshift at ck=0
        if (ck < 3) {
            prefetch_w(sm, W_OFF2(buf ^ 1), mat, ck + 1);
            CP_COMMIT();
        }
        // convert X chunk hi+lo (overlaps W cp.async)
        {
            int r = tid >> 1, half = tid & 1;
            int gr = row0 + r;
            int gc = ck * 32 + half * 16;
            uint4 hv = make_uint4(0, 0, 0, 0), lv = make_uint4(0, 0, 0, 0);
            uint4 hv2 = hv, lv2 = lv;
            if (gr < NN) {
                const float* srcp = g_h + gr * DD + gc;
                uint32_t hp[8], lp[8];
                #pragma unroll
                for (int i = 0; i < 8; i++) {
                    float v0 = fmaxf(fmaf(srcp[2 * i], sscale[gc + 2 * i], sshift[gc + 2 * i]), 0.f);
                    float v1 = fmaxf(fmaf(srcp[2 * i + 1], sscale[gc + 2 * i + 1], sshift[gc + 2 * i + 1]), 0.f);
                    __nv_bfloat16 h0 = __float2bfloat16(v0), h1 = __float2bfloat16(v1);
                    __nv_bfloat16 l0 = __float2bfloat16(v0 - __bfloat162float(h0));
                    __nv_bfloat16 l1 = __float2bfloat16(v1 - __bfloat162float(h1));
                    hp[i] = pack2bf(h0, h1);
                    lp[i] = pack2bf(l0, l1);
                }
                hv = make_uint4(hp[0], hp[1], hp[2], hp[3]);
                hv2 = make_uint4(hp[4], hp[5], hp[6], hp[7]);
                lv = make_uint4(lp[0], lp[1], lp[2], lp[3]);
                lv2 = make_uint4(lp[4], lp[5], lp[6], lp[7]);
            }
            *(uint4*)(xhi + r * PITCH + half * 16)     = hv;
            *(uint4*)(xhi + r * PITCH + half * 16 + 8) = hv2;
            *(uint4*)(xlo + r * PITCH + half * 16)     = lv;
            *(uint4*)(xlo + r * PITCH + half * 16 + 8) = lv2;
        }
        if (ck < 3) CP_WAIT(1); else CP_WAIT(0);
        __syncthreads();
        uint32_t axh = smem_u32(xhi);
        uint32_t axl = smem_u32(xlo);
        uint32_t bwh = smem_u32(sm + W_OFF2(buf));
        do_pass2(axh, bwh, bwh + PS, wm, wn, lane, acc);
        do_pass1(axl, bwh, wm, wn, lane, acc);
        buf ^= 1;
    }

    #pragma unroll
    for (int mt = 0; mt < 4; mt++) {
        int r0 = row0 + wm * 64 + mt * 16 + (lane >> 2);
        int r1 = r0 + 8;
        #pragma unroll
        for (int nt = 0; nt < 4; nt++) {
            int c = wn * 32 + nt * 8 + (lane & 3) * 2;
            float b0 = b[c], b1 = b[c + 1];
            float v0 = acc[mt][nt][0] + b0, v1 = acc[mt][nt][1] + b1;
            float v2 = acc[mt][nt][2] + b0, v3 = acc[mt][nt][3] + b1;
            if (do_relu) {
                v0 = fmaxf(v0, 0.f); v1 = fmaxf(v1, 0.f);
                v2 = fmaxf(v2, 0.f); v3 = fmaxf(v3, 0.f);
            }
            if (r0 < NN) *(float2*)(Out + r0 * DD + c) = make_float2(v0, v1);
            if (r1 < NN) *(float2*)(Out + r1 * DD + c) = make_float2(v2, v3);
        }
    }
}

extern "C" void kernel_launch(void* const* d_in, const int* in_sizes, int n_in,
                              void* d_out, int out_size) {
    (void)in_sizes; (void)n_in; (void)out_size;
    const float* x     = (const float*)d_in[0];
    const int*   ei    = (const int*)d_in[1];   // int32 (JAX x64 disabled)
    const float* W1    = (const float*)d_in[2];
    const float* b1    = (const float*)d_in[3];
    const float* gamma = (const float*)d_in[4];
    const float* beta  = (const float*)d_in[5];
    const float* W2    = (const float*)d_in[6];
    const float* b2    = (const float*)d_in[7];
    const float* eps   = (const float*)d_in[8];
    float* out = (float*)d_out;

    const int* src = ei;
    const int* dst = ei + EE;

    cudaFuncSetAttribute(k_gemm1_p, cudaFuncAttributeMaxDynamicSharedMemorySize, SM1_TOT);
    cudaFuncSetAttribute(k_gemm2_p, cudaFuncAttributeMaxDynamicSharedMemorySize, SM2_TOT);

    k_prep<<<6 + (NN + 255) / 256, 256>>>(W1, W2);
    k_hist<<<(EE + 255) / 256, 256>>>(dst);
    k_scan<<<1, 1024>>>();
    k_fill<<<(EE + 255) / 256, 256>>>(src, dst);

    for (int l = 0; l < 3; l++) {
        int use_ext = (l == 0) ? 1 : 0;
        int internal = (l == 2) ? 0 : 1;
        k_gather<<<(NN * 32 + 255) / 256, 256>>>(x, use_ext, eps + l);
        k_gemm1_p<<<NBT, 256, SM1_TOT>>>(l, b1 + l * DD);
        k_gemm2_p<<<NBT, 256, SM2_TOT>>>(3 + l, gamma + l * DD, beta + l * DD,
                                         b2 + l * DD, out, internal, (l < 2) ? 1 : 0);
    }
}

// round 15
// speedup vs baseline: 1.2488x; 1.0148x over previous
#include <cuda_runtime.h>
#include <cuda_bf16.h>
#include <cstdint>

#define NN 50000
#define DD 128
#define EE 800000
#define NBT 782           // ceil(50000/64) GEMM row tiles (M=64)

typedef unsigned short ushortt;

// ---------------- scratch (device globals) ----------------
__device__ __align__(16) float g_h[NN * DD];
__device__ __align__(16) float g_x[NN * DD];
__device__ __align__(16) __nv_bfloat16 g_xhi[NN * DD];  // combined feat, bf16 hi plane
__device__ __align__(16) __nv_bfloat16 g_xlo[NN * DD];  // combined feat, bf16 lo plane
__device__ float g_sum[DD];
__device__ float g_sumsq[DD];
// CSR
__device__ int g_cnt[NN];
__device__ int g_row[NN + 1];
__device__ int g_cur[NN];
__device__ int g_adj[EE];
// W images, transposed to [n][k] row-major bf16, hi/lo split; 6 mats
__device__ __align__(16) __nv_bfloat16 g_whi[6 * 16384];
__device__ __align__(16) __nv_bfloat16 g_wlo[6 * 16384];

// ---------------- helpers ----------------
__device__ __forceinline__ uint32_t smem_u32(const void* p) {
    uint32_t a;
    asm("{ .reg .u64 t; cvta.to.shared.u64 t, %1; cvt.u32.u64 %0, t; }" : "=r"(a) : "l"(p));
    return a;
}
__device__ __forceinline__ uint32_t pack2bf(__nv_bfloat16 a, __nv_bfloat16 b) {
    return (uint32_t)__bfloat16_as_ushort(a) | ((uint32_t)__bfloat16_as_ushort(b) << 16);
}
__device__ __forceinline__ void ldm_x4(uint32_t addr, uint32_t* r) {
    asm volatile("ldmatrix.sync.aligned.m8n8.x4.shared.b16 {%0,%1,%2,%3}, [%4];"
        : "=r"(r[0]), "=r"(r[1]), "=r"(r[2]), "=r"(r[3]) : "r"(addr));
}
__device__ __forceinline__ void mma_bf16(float* d, const uint32_t* a, const uint32_t* b) {
    asm volatile("mma.sync.aligned.m16n8k16.row.col.f32.bf16.bf16.f32 "
        "{%0,%1,%2,%3}, {%4,%5,%6,%7}, {%8,%9}, {%0,%1,%2,%3};"
        : "+f"(d[0]), "+f"(d[1]), "+f"(d[2]), "+f"(d[3])
        : "r"(a[0]), "r"(a[1]), "r"(a[2]), "r"(a[3]), "r"(b[0]), "r"(b[1]));
}
__device__ __forceinline__ void cp16(uint32_t sm, const void* g) {
    asm volatile("cp.async.ca.shared.global [%0], [%1], 16;" :: "r"(sm), "l"(g));
}
#define CP_COMMIT() asm volatile("cp.async.commit_group;" ::: "memory")
#define CP_WAIT(n)  asm volatile("cp.async.wait_group %0;" :: "n"(n) : "memory")

#define PITCH 40                 // bf16 per smem plane row (80B: conflict-free ldmatrix)
#define PSW 10240                // W plane bytes: 128*PITCH*2
#define PSX 5120                 // X plane bytes: 64*PITCH*2  (M=64 tiles)
// GEMM1 smem: [Xhi|Xlo](buf0) [Xhi|Xlo](buf1) [Whi|Wlo](buf0) [Whi|Wlo](buf1)
#define X_OFF(b)  ((b) * 2 * PSX)
#define W_OFF1(b) (4 * PSX + (b) * 2 * PSW)
#define SM1_TOT   (4 * PSX + 4 * PSW)     // 61440 -> 3 blocks/SM
// GEMM2 smem: [Xhi|Xlo] [Whi|Wlo](buf0) [Whi|Wlo](buf1) [scale|shift]
#define W_OFF2(b) (2 * PSX + (b) * 2 * PSW)
#define SC_OFF    (2 * PSX + 4 * PSW)
#define SM2_TOT   (2 * PSX + 4 * PSW + 1024)  // 52224 -> 4 blocks/SM

// ---------------- CSR build + weight prep ----------------
__global__ void __launch_bounds__(256) k_prep(const float* __restrict__ W1,
                                              const float* __restrict__ W2) {
    if (blockIdx.x < 6) {
        int m = blockIdx.x;
        const float* src = (m < 3) ? (W1 + m * 16384) : (W2 + (m - 3) * 16384);
        __nv_bfloat16* hi = g_whi + m * 16384;
        __nv_bfloat16* lo = g_wlo + m * 16384;
        for (int i = threadIdx.x; i < 16384; i += 256) {
            int k = i >> 7, n = i & 127;
            float v = src[i];
            __nv_bfloat16 h = __float2bfloat16(v);
            __nv_bfloat16 l = __float2bfloat16(v - __bfloat162float(h));
            hi[n * 128 + k] = h;
            lo[n * 128 + k] = l;
        }
    } else {
        int i = (blockIdx.x - 6) * 256 + threadIdx.x;
        if (i < NN) g_cnt[i] = 0;
    }
}
__global__ void k_hist(const int* __restrict__ dst) {
    int e = blockIdx.x * blockDim.x + threadIdx.x;
    if (e < EE) atomicAdd(&g_cnt[dst[e]], 1);
}
__global__ void __launch_bounds__(1024) k_scan() {
    __shared__ int sm[1024];
    const int CH = 49;
    int t = threadIdx.x;
    int beg = t * CH;
    int tot = 0;
    for (int i = beg; i < beg + CH && i < NN; i++) tot += g_cnt[i];
    sm[t] = tot;
    __syncthreads();
    for (int off = 1; off < 1024; off <<= 1) {
        int v = (t >= off) ? sm[t - off] : 0;
        __syncthreads();
        sm[t] += v;
        __syncthreads();
    }
    int base = sm[t] - tot;
    for (int i = beg; i < beg + CH && i < NN; i++) {
        g_row[i] = base; g_cur[i] = 0; base += g_cnt[i];
    }
    if (t == 1023) g_row[NN] = sm[1023];
}
__global__ void k_fill(const int* __restrict__ src, const int* __restrict__ dst) {
    int e = blockIdx.x * blockDim.x + threadIdx.x;
    if (e >= EE) return;
    int d = dst[e];
    int pos = atomicAdd(&g_cur[d], 1);
    g_adj[g_row[d] + pos] = src[e];
}

// ---------------- gather + combine -> bf16 hi/lo planes; zeroes BN stats ----------------
__global__ void k_gather(const float* __restrict__ Xext, int use_ext,
                         const float* __restrict__ epsp) {
    if (blockIdx.x == 0 && threadIdx.x < DD) {
        g_sum[threadIdx.x] = 0.f;
        g_sumsq[threadIdx.x] = 0.f;
    }
    const float* X = use_ext ? Xext : (const float*)g_x;
    int gid = blockIdx.x * blockDim.x + threadIdx.x;
    int node = gid >> 5;
    if (node >= NN) return;
    int lane = gid & 31;
    int beg = g_row[node], end = g_row[node + 1];
    float4 a = make_float4(0.f, 0.f, 0.f, 0.f);
    for (int i = beg; i < end; i++) {
        int s = g_adj[i];
        float4 v = ((const float4*)X)[s * 32 + lane];
        a.x += v.x; a.y += v.y; a.z += v.z; a.w += v.w;
    }
    float4 xv = ((const float4*)X)[node * 32 + lane];
    float pa = a.x * a.x + a.y * a.y + a.z * a.z + a.w * a.w;
    float px = xv.x * xv.x + xv.y * xv.y + xv.z * xv.z + xv.w * xv.w;
    #pragma unroll
    for (int off = 16; off; off >>= 1) {
        pa += __shfl_xor_sync(0xffffffffu, pa, off);
        px += __shfl_xor_sync(0xffffffffu, px, off);
    }
    float ia = 1.f / fmaxf(sqrtf(pa), 1e-12f);
    float ix = (1.f + epsp[0]) / fmaxf(sqrtf(px), 1e-12f);
    float o[4];
    o[0] = a.x * ia + xv.x * ix;
    o[1] = a.y * ia + xv.y * ix;
    o[2] = a.z * ia + xv.z * ix;
    o[3] = a.w * ia + xv.w * ix;
    __nv_bfloat16 h[4], l[4];
    #pragma unroll
    for (int j = 0; j < 4; j++) {
        h[j] = __float2bfloat16(o[j]);
        l[j] = __float2bfloat16(o[j] - __bfloat162float(h[j]));
    }
    *(uint2*)(g_xhi + node * DD + lane * 4) = make_uint2(pack2bf(h[0], h[1]), pack2bf(h[2], h[3]));
    *(uint2*)(g_xlo + node * DD + lane * 4) = make_uint2(pack2bf(l[0], l[1]), pack2bf(l[2], l[3]));
}

// ---------------- shared GEMM machinery ----------------
__device__ __forceinline__ void prefetch_w(char* sm, uint32_t woff, int mat, int ck) {
    int tid = threadIdx.x;
    const __nv_bfloat16* gh = g_whi + mat * 16384 + ck * 32;
    const __nv_bfloat16* gl = g_wlo + mat * 16384 + ck * 32;
    uint32_t sh = smem_u32(sm + woff);
    uint32_t sl = sh + PSW;
    for (int i = tid; i < 512; i += 256) {
        int row = i >> 2, q = i & 3;
        uint32_t so = (uint32_t)(row * PITCH + q * 8) * 2;
        cp16(sh + so, gh + row * 128 + q * 8);
        cp16(sl + so, gl + row * 128 + q * 8);
    }
}

// X chunk for 64-row tile: 64 rows x 32 cols, hi+lo planes
__device__ __forceinline__ void prefetch_x_guarded(char* sm, uint32_t xoff, int row0, int ck) {
    int tid = threadIdx.x;
    uint32_t sh = smem_u32(sm + xoff);
    {
        int i = tid;   // 256 threads cover 64 rows x 4 col-quarters exactly
        int row = i >> 2, q = i & 3;
        int gr = row0 + row;
        uint32_t so = (uint32_t)(row * PITCH + q * 8) * 2;
        if (gr < NN) {
            cp16(sh + so, g_xhi + gr * DD + ck * 32 + q * 8);
            cp16(sh + PSX + so, g_xlo + gr * DD + ck * 32 + q * 8);
        } else {
            uint4 z = make_uint4(0, 0, 0, 0);
            *(uint4*)(sm + xoff + so) = z;
            *(uint4*)(sm + xoff + PSX + so) = z;
        }
    }
}

// A loaded once, multiplied by both W planes (hi+lo); M=64 tile: mt<2
__device__ __forceinline__ void do_pass2(uint32_t abase, uint32_t bwh, uint32_t bwl,
                                         int wm, int wn, int lane, float acc[2][4][4]) {
    #pragma unroll
    for (int ks = 0; ks < 2; ks++) {
        uint32_t af[2][4];
        #pragma unroll
        for (int mt = 0; mt < 2; mt++) {
            int row = wm * 32 + mt * 16 + (lane & 7) + ((lane >> 3) & 1) * 8;
            int col = ks * 16 + ((lane >> 4) & 1) * 8;
            ldm_x4(abase + (row * PITCH + col) * 2, af[mt]);
        }
        uint32_t bh[4][2], bl[4][2];
        #pragma unroll
        for (int jp = 0; jp < 2; jp++) {
            int n = wn * 32 + jp * 16 + ((lane >> 4) & 1) * 8 + (lane & 7);
            int col = ks * 16 + ((lane >> 3) & 1) * 8;
            uint32_t r4[4];
            ldm_x4(bwh + (n * PITCH + col) * 2, r4);
            bh[jp * 2][0] = r4[0]; bh[jp * 2][1] = r4[1];
            bh[jp * 2 + 1][0] = r4[2]; bh[jp * 2 + 1][1] = r4[3];
            ldm_x4(bwl + (n * PITCH + col) * 2, r4);
            bl[jp * 2][0] = r4[0]; bl[jp * 2][1] = r4[1];
            bl[jp * 2 + 1][0] = r4[2]; bl[jp * 2 + 1][1] = r4[3];
        }
        #pragma unroll
        for (int mt = 0; mt < 2; mt++)
            #pragma unroll
            for (int nt = 0; nt < 4; nt++) {
                mma_bf16(acc[mt][nt], af[mt], bh[nt]);
                mma_bf16(acc[mt][nt], af[mt], bl[nt]);
            }
    }
}

// single pass: Xlo against W-hi
__device__ __forceinline__ void do_pass1(uint32_t abase, uint32_t bwh,
                                         int wm, int wn, int lane, float acc[2][4][4]) {
    #pragma unroll
    for (int ks = 0; ks < 2; ks++) {
        uint32_t af[2][4];
        #pragma unroll
        for (int mt = 0; mt < 2; mt++) {
            int row = wm * 32 + mt * 16 + (lane & 7) + ((lane >> 3) & 1) * 8;
            int col = ks * 16 + ((lane >> 4) & 1) * 8;
            ldm_x4(abase + (row * PITCH + col) * 2, af[mt]);
        }
        uint32_t bf[4][2];
        #pragma unroll
        for (int jp = 0; jp < 2; jp++) {
            int n = wn * 32 + jp * 16 + ((lane >> 4) & 1) * 8 + (lane & 7);
            int col = ks * 16 + ((lane >> 3) & 1) * 8;
            uint32_t r4[4];
            ldm_x4(bwh + (n * PITCH + col) * 2, r4);
            bf[jp * 2][0] = r4[0]; bf[jp * 2][1] = r4[1];
            bf[jp * 2 + 1][0] = r4[2]; bf[jp * 2 + 1][1] = r4[3];
        }
        #pragma unroll
        for (int mt = 0; mt < 2; mt++)
            #pragma unroll
            for (int nt = 0; nt < 4; nt++)
                mma_bf16(acc[mt][nt], af[mt], bf[nt]);
    }
}

extern __shared__ __align__(16) char dsm[];

// ---------------- GEMM1: h = comb @ W1 + b1 -> g_h, BN stats via atomics ----------------
__global__ void __launch_bounds__(256) k_gemm1_p(int mat, const float* __restrict__ b) {
    char* sm = dsm;
    int tid = threadIdx.x;
    int wid = tid >> 5, lane = tid & 31;
    int wm = wid & 1, wn = wid >> 1;
    int row0 = blockIdx.x * 64;

    float acc[2][4][4];
    #pragma unroll
    for (int mt = 0; mt < 2; mt++)
        #pragma unroll
        for (int nt = 0; nt < 4; nt++)
            #pragma unroll
            for (int i = 0; i < 4; i++) acc[mt][nt][i] = 0.f;

    prefetch_x_guarded(sm, X_OFF(0), row0, 0);
    prefetch_w(sm, W_OFF1(0), mat, 0);
    CP_COMMIT();

    int buf = 0;
    for (int ck = 0; ck < 4; ck++) {
        __syncthreads();
        if (ck < 3) {
            prefetch_x_guarded(sm, X_OFF(buf ^ 1), row0, ck + 1);
            prefetch_w(sm, W_OFF1(buf ^ 1), mat, ck + 1);
            CP_COMMIT();
            CP_WAIT(1);
        } else {
            CP_WAIT(0);
        }
        __syncthreads();
        uint32_t axh = smem_u32(sm + X_OFF(buf));
        uint32_t axl = axh + PSX;
        uint32_t bwh = smem_u32(sm + W_OFF1(buf));
        do_pass2(axh, bwh, bwh + PSW, wm, wn, lane, acc);  // Xhi*(Whi+Wlo)
        do_pass1(axl, bwh, wm, wn, lane, acc);             // Xlo*Whi
        buf ^= 1;
    }

    // epilogue: bias, store h, BN partials -> global atomics
    float ls[4][2], lq[4][2];
    #pragma unroll
    for (int nt = 0; nt < 4; nt++) { ls[nt][0] = ls[nt][1] = lq[nt][0] = lq[nt][1] = 0.f; }
    #pragma unroll
    for (int mt = 0; mt < 2; mt++) {
        int r0 = row0 + wm * 32 + mt * 16 + (lane >> 2);
        int r1 = r0 + 8;
        #pragma unroll
        for (int nt = 0; nt < 4; nt++) {
            int c = wn * 32 + nt * 8 + (lane & 3) * 2;
            float b0 = b[c], b1 = b[c + 1];
            float v0 = acc[mt][nt][0] + b0, v1 = acc[mt][nt][1] + b1;
            float v2 = acc[mt][nt][2] + b0, v3 = acc[mt][nt][3] + b1;
            if (r0 < NN) {
                *(float2*)(g_h + r0 * DD + c) = make_float2(v0, v1);
                ls[nt][0] += v0; ls[nt][1] += v1;
                lq[nt][0] += v0 * v0; lq[nt][1] += v1 * v1;
            }
            if (r1 < NN) {
                *(float2*)(g_h + r1 * DD + c) = make_float2(v2, v3);
                ls[nt][0] += v2; ls[nt][1] += v3;
                lq[nt][0] += v2 * v2; lq[nt][1] += v3 * v3;
            }
        }
    }
    #pragma unroll
    for (int off = 4; off <= 16; off <<= 1) {
        #pragma unroll
        for (int nt = 0; nt < 4; nt++) {
            ls[nt][0] += __shfl_xor_sync(0xffffffffu, ls[nt][0], off);
            ls[nt][1] += __shfl_xor_sync(0xffffffffu, ls[nt][1], off);
            lq[nt][0] += __shfl_xor_sync(0xffffffffu, lq[nt][0], off);
            lq[nt][1] += __shfl_xor_sync(0xffffffffu, lq[nt][1], off);
        }
    }
    __syncthreads();
    float* ssum = (float*)sm;
    float* ssq  = ssum + 256;
    if (lane < 4) {
        #pragma unroll
        for (int nt = 0; nt < 4; nt++) {
            ssum[wid * 32 + nt * 8 + lane * 2]     = ls[nt][0];
            ssum[wid * 32 + nt * 8 + lane * 2 + 1] = ls[nt][1];
            ssq[wid * 32 + nt * 8 + lane * 2]      = lq[nt][0];
            ssq[wid * 32 + nt * 8 + lane * 2 + 1]  = lq[nt][1];
        }
    }
    __syncthreads();
    if (tid < DD) {
        int w0 = (tid >> 5) * 2;
        float s = ssum[w0 * 32 + (tid & 31)] + ssum[(w0 + 1) * 32 + (tid & 31)];
        float q = ssq[w0 * 32 + (tid & 31)] + ssq[(w0 + 1) * 32 + (tid & 31)];
        atomicAdd(&g_sum[tid], s);
        atomicAdd(&g_sumsq[tid], q);
    }
}

// ---------------- GEMM2: out = relu?(bn_relu(h) @ W2 + b2); BN finalize inline ----------------
__global__ void __launch_bounds__(256) k_gemm2_p(int mat, const float* __restrict__ gamma,
                                                 const float* __restrict__ beta,
                                                 const float* __restrict__ b,
                                                 float* __restrict__ OutExt,
                                                 int internal, int do_relu) {
    char* sm = dsm;
    float* Out = internal ? (float*)g_x : OutExt;
    int tid = threadIdx.x;
    int wid = tid >> 5, lane = tid & 31;
    int wm = wid & 1, wn = wid >> 1;
    int row0 = blockIdx.x * 64;

    float acc[2][4][4];
    #pragma unroll
    for (int mt = 0; mt < 2; mt++)
        #pragma unroll
        for (int nt = 0; nt < 4; nt++)
            #pragma unroll
            for (int i = 0; i < 4; i++) acc[mt][nt][i] = 0.f;

    prefetch_w(sm, W_OFF2(0), mat, 0);
    CP_COMMIT();

    // inline BN finalize: scale/shift into smem (overlaps W prefetch)
    float* sscale = (float*)(sm + SC_OFF);
    float* sshift = sscale + DD;
    if (tid < DD) {
        float mean = g_sum[tid] * (1.f / NN);
        float var  = g_sumsq[tid] * (1.f / NN) - mean * mean;
        float sc = gamma[tid] * rsqrtf(var + 1e-5f);
        sscale[tid] = sc;
        sshift[tid] = beta[tid] - mean * sc;
    }

    ushortt* xhi = (ushortt*)sm;
    ushortt* xlo = (ushortt*)(sm + PSX);
    int buf = 0;
    for (int ck = 0; ck < 4; ck++) {
        __syncthreads();   // prev passes done; also publishes sscale/sshift at ck=0
        if (ck < 3) {
            prefetch_w(sm, W_OFF2(buf ^ 1), mat, ck + 1);
            CP_COMMIT();
        }
        // convert X chunk hi+lo: 64 rows x 32 cols, 4 threads/row x 8 cols
        {
            int r = tid >> 2, q = tid & 3;
            int gr = row0 + r;
            int gc = ck * 32 + q * 8;
            uint4 hv = make_uint4(0, 0, 0, 0), lv = make_uint4(0, 0, 0, 0);
            if (gr < NN) {
                const float* srcp = g_h + gr * DD + gc;
                uint32_t hp[4], lp[4];
                #pragma unroll
                for (int i = 0; i < 4; i++) {
                    float v0 = fmaxf(fmaf(srcp[2 * i], sscale[gc + 2 * i], sshift[gc + 2 * i]), 0.f);
                    float v1 = fmaxf(fmaf(srcp[2 * i + 1], sscale[gc + 2 * i + 1], sshift[gc + 2 * i + 1]), 0.f);
                    __nv_bfloat16 h0 = __float2bfloat16(v0), h1 = __float2bfloat16(v1);
                    __nv_bfloat16 l0 = __float2bfloat16(v0 - __bfloat162float(h0));
                    __nv_bfloat16 l1 = __float2bfloat16(v1 - __bfloat162float(h1));
                    hp[i] = pack2bf(h0, h1);
                    lp[i] = pack2bf(l0, l1);
                }
                hv = make_uint4(hp[0], hp[1], hp[2], hp[3]);
                lv = make_uint4(lp[0], lp[1], lp[2], lp[3]);
            }
            *(uint4*)(xhi + r * PITCH + q * 8) = hv;
            *(uint4*)(xlo + r * PITCH + q * 8) = lv;
        }
        if (ck < 3) CP_WAIT(1); else CP_WAIT(0);
        __syncthreads();
        uint32_t axh = smem_u32(xhi);
        uint32_t axl = smem_u32(xlo);
        uint32_t bwh = smem_u32(sm + W_OFF2(buf));
        do_pass2(axh, bwh, bwh + PSW, wm, wn, lane, acc);
        do_pass1(axl, bwh, wm, wn, lane, acc);
        buf ^= 1;
    }

    #pragma unroll
    for (int mt = 0; mt < 2; mt++) {
        int r0 = row0 + wm * 32 + mt * 16 + (lane >> 2);
        int r1 = r0 + 8;
        #pragma unroll
        for (int nt = 0; nt < 4; nt++) {
            int c = wn * 32 + nt * 8 + (lane & 3) * 2;
            float b0 = b[c], b1 = b[c + 1];
            float v0 = acc[mt][nt][0] + b0, v1 = acc[mt][nt][1] + b1;
            float v2 = acc[mt][nt][2] + b0, v3 = acc[mt][nt][3] + b1;
            if (do_relu) {
                v0 = fmaxf(v0, 0.f); v1 = fmaxf(v1, 0.f);
                v2 = fmaxf(v2, 0.f); v3 = fmaxf(v3, 0.f);
            }
            if (r0 < NN) *(float2*)(Out + r0 * DD + c) = make_float2(v0, v1);
            if (r1 < NN) *(float2*)(Out + r1 * DD + c) = make_float2(v2, v3);
        }
    }
}

extern "C" void kernel_launch(void* const* d_in, const int* in_sizes, int n_in,
                              void* d_out, int out_size) {
    (void)in_sizes; (void)n_in; (void)out_size;
    const float* x     = (const float*)d_in[0];
    const int*   ei    = (const int*)d_in[1];   // int32 (JAX x64 disabled)
    const float* W1    = (const float*)d_in[2];
    const float* b1    = (const float*)d_in[3];
    const float* gamma = (const float*)d_in[4];
    const float* beta  = (const float*)d_in[5];
    const float* W2    = (const float*)d_in[6];
    const float* b2    = (const float*)d_in[7];
    const float* eps   = (const float*)d_in[8];
    float* out = (float*)d_out;

    const int* src = ei;
    const int* dst = ei + EE;

    cudaFuncSetAttribute(k_gemm1_p, cudaFuncAttributeMaxDynamicSharedMemorySize, SM1_TOT);
    cudaFuncSetAttribute(k_gemm2_p, cudaFuncAttributeMaxDynamicSharedMemorySize, SM2_TOT);

    k_prep<<<6 + (NN + 255) / 256, 256>>>(W1, W2);
    k_hist<<<(EE + 255) / 256, 256>>>(dst);
    k_scan<<<1, 1024>>>();
    k_fill<<<(EE + 255) / 256, 256>>>(src, dst);

    for (int l = 0; l < 3; l++) {
        int use_ext = (l == 0) ? 1 : 0;
        int internal = (l == 2) ? 0 : 1;
        k_gather<<<(NN * 32 + 255) / 256, 256>>>(x, use_ext, eps + l);
        k_gemm1_p<<<NBT, 256, SM1_TOT>>>(l, b1 + l * DD);
        k_gemm2_p<<<NBT, 256, SM2_TOT>>>(3 + l, gamma + l * DD, beta + l * DD,
                                         b2 + l * DD, out, internal, (l < 2) ? 1 : 0);
    }
}

// round 16
// speedup vs baseline: 1.5231x; 1.2197x over previous
#include <cuda_runtime.h>
#include <cuda_bf16.h>
#include <cstdint>

#define NN 50000
#define DD 128
#define EE 800000
#define NBT 782           // ceil(50000/64) GEMM row tiles (M=64)
#define SCB 49            // scan blocks: 49*1024 >= NN

typedef unsigned short ushortt;

// ---------------- scratch (device globals) ----------------
__device__ __align__(16) float g_h[NN * DD];
__device__ __align__(16) float g_x[NN * DD];
__device__ __align__(16) __nv_bfloat16 g_xhi[NN * DD];  // combined feat, bf16 hi plane
__device__ __align__(16) __nv_bfloat16 g_xlo[NN * DD];  // combined feat, bf16 lo plane
__device__ float g_sum[DD];
__device__ float g_sumsq[DD];
// CSR
__device__ int g_cnt[NN];
__device__ int g_row[NN + 1];
__device__ int g_cur[NN];
__device__ int g_adj[EE];
__device__ int g_bsum[SCB];
__device__ int g_boff[SCB];
// W images, transposed to [n][k] row-major bf16, hi/lo split; 6 mats
__device__ __align__(16) __nv_bfloat16 g_whi[6 * 16384];
__device__ __align__(16) __nv_bfloat16 g_wlo[6 * 16384];

// ---------------- helpers ----------------
__device__ __forceinline__ uint32_t smem_u32(const void* p) {
    uint32_t a;
    asm("{ .reg .u64 t; cvta.to.shared.u64 t, %1; cvt.u32.u64 %0, t; }" : "=r"(a) : "l"(p));
    return a;
}
__device__ __forceinline__ uint32_t pack2bf(__nv_bfloat16 a, __nv_bfloat16 b) {
    return (uint32_t)__bfloat16_as_ushort(a) | ((uint32_t)__bfloat16_as_ushort(b) << 16);
}
__device__ __forceinline__ void ldm_x4(uint32_t addr, uint32_t* r) {
    asm volatile("ldmatrix.sync.aligned.m8n8.x4.shared.b16 {%0,%1,%2,%3}, [%4];"
        : "=r"(r[0]), "=r"(r[1]), "=r"(r[2]), "=r"(r[3]) : "r"(addr));
}
__device__ __forceinline__ void mma_bf16(float* d, const uint32_t* a, const uint32_t* b) {
    asm volatile("mma.sync.aligned.m16n8k16.row.col.f32.bf16.bf16.f32 "
        "{%0,%1,%2,%3}, {%4,%5,%6,%7}, {%8,%9}, {%0,%1,%2,%3};"
        : "+f"(d[0]), "+f"(d[1]), "+f"(d[2]), "+f"(d[3])
        : "r"(a[0]), "r"(a[1]), "r"(a[2]), "r"(a[3]), "r"(b[0]), "r"(b[1]));
}
__device__ __forceinline__ void cp16(uint32_t sm, const void* g) {
    asm volatile("cp.async.ca.shared.global [%0], [%1], 16;" :: "r"(sm), "l"(g));
}
#define CP_COMMIT() asm volatile("cp.async.commit_group;" ::: "memory")
#define CP_WAIT(n)  asm volatile("cp.async.wait_group %0;" :: "n"(n) : "memory")

#define PITCH 40                 // bf16 per smem plane row (80B: conflict-free ldmatrix)
#define PSW 10240                // W plane bytes: 128*PITCH*2
#define PSX 5120                 // X plane bytes: 64*PITCH*2  (M=64 tiles)
// GEMM1 smem: [Xhi|Xlo](buf0) [Xhi|Xlo](buf1) [Whi|Wlo](buf0) [Whi|Wlo](buf1)
#define X_OFF(b)  ((b) * 2 * PSX)
#define W_OFF1(b) (4 * PSX + (b) * 2 * PSW)
#define SM1_TOT   (4 * PSX + 4 * PSW)     // 61440
// GEMM2 smem: [Xhi|Xlo] [Whi|Wlo](buf0) [Whi|Wlo](buf1) [scale|shift]
#define W_OFF2(b) (2 * PSX + (b) * 2 * PSW)
#define SC_OFF    (2 * PSX + 4 * PSW)
#define SM2_TOT   (2 * PSX + 4 * PSW + 1024)  // 52224

// ---------------- setup: weight prep + zero cnt/cur ----------------
__global__ void __launch_bounds__(256) k_prep(const float* __restrict__ W1,
                                              const float* __restrict__ W2) {
    if (blockIdx.x < 6) {
        int m = blockIdx.x;
        const float* src = (m < 3) ? (W1 + m * 16384) : (W2 + (m - 3) * 16384);
        __nv_bfloat16* hi = g_whi + m * 16384;
        __nv_bfloat16* lo = g_wlo + m * 16384;
        for (int i = threadIdx.x; i < 16384; i += 256) {
            int k = i >> 7, n = i & 127;
            float v = src[i];
            __nv_bfloat16 h = __float2bfloat16(v);
            __nv_bfloat16 l = __float2bfloat16(v - __bfloat162float(h));
            hi[n * 128 + k] = h;
            lo[n * 128 + k] = l;
        }
    } else {
        int i = (blockIdx.x - 6) * 256 + threadIdx.x;
        if (i < NN) { g_cnt[i] = 0; g_cur[i] = 0; }
    }
}
__global__ void k_hist(const int* __restrict__ dst) {
    int e = blockIdx.x * blockDim.x + threadIdx.x;
    if (e < EE) atomicAdd(&g_cnt[dst[e]], 1);
}

// ---------------- parallel 3-stage scan ----------------
__global__ void __launch_bounds__(1024) k_scan_part() {
    __shared__ int sm[1024];
    int t = threadIdx.x;
    int i = blockIdx.x * 1024 + t;
    int c = (i < NN) ? g_cnt[i] : 0;
    sm[t] = c;
    __syncthreads();
    #pragma unroll
    for (int off = 1; off < 1024; off <<= 1) {
        int v = (t >= off) ? sm[t - off] : 0;
        __syncthreads();
        sm[t] += v;
        __syncthreads();
    }
    if (i < NN) g_row[i] = sm[t] - c;   // local exclusive
    if (t == 1023) g_bsum[blockIdx.x] = sm[1023];
}
__global__ void k_scan_top() {
    __shared__ int sm[64];
    int t = threadIdx.x;
    sm[t] = (t < SCB) ? g_bsum[t] : 0;
    __syncthreads();
    #pragma unroll
    for (int off = 1; off < 64; off <<= 1) {
        int v = (t >= off) ? sm[t - off] : 0;
        __syncthreads();
        sm[t] += v;
        __syncthreads();
    }
    if (t < SCB) g_boff[t] = sm[t] - g_bsum[t];   // exclusive
    if (t == 0) g_row[NN] = EE;
}
__global__ void __launch_bounds__(1024) k_scan_add() {
    int i = blockIdx.x * 1024 + threadIdx.x;
    if (i < NN) g_row[i] += g_boff[blockIdx.x];
}

__global__ void k_fill(const int* __restrict__ src, const int* __restrict__ dst) {
    int e = blockIdx.x * blockDim.x + threadIdx.x;
    if (e >= EE) return;
    int d = dst[e];
    int pos = atomicAdd(&g_cur[d], 1);
    g_adj[g_row[d] + pos] = src[e];
}

// ---------------- gather + combine -> bf16 hi/lo planes; zeroes BN stats ----------------
__global__ void k_gather(const float* __restrict__ Xext, int use_ext,
                         const float* __restrict__ epsp) {
    if (blockIdx.x == 0 && threadIdx.x < DD) {
        g_sum[threadIdx.x] = 0.f;
        g_sumsq[threadIdx.x] = 0.f;
    }
    const float* X = use_ext ? Xext : (const float*)g_x;
    int gid = blockIdx.x * blockDim.x + threadIdx.x;
    int node = gid >> 5;
    if (node >= NN) return;
    int lane = gid & 31;
    int beg = g_row[node], end = g_row[node + 1];
    float4 a = make_float4(0.f, 0.f, 0.f, 0.f);
    #pragma unroll 4
    for (int i = beg; i < end; i++) {
        int s = g_adj[i];
        float4 v = ((const float4*)X)[s * 32 + lane];
        a.x += v.x; a.y += v.y; a.z += v.z; a.w += v.w;
    }
    float4 xv = ((const float4*)X)[node * 32 + lane];
    float pa = a.x * a.x + a.y * a.y + a.z * a.z + a.w * a.w;
    float px = xv.x * xv.x + xv.y * xv.y + xv.z * xv.z + xv.w * xv.w;
    #pragma unroll
    for (int off = 16; off; off >>= 1) {
        pa += __shfl_xor_sync(0xffffffffu, pa, off);
        px += __shfl_xor_sync(0xffffffffu, px, off);
    }
    float ia = 1.f / fmaxf(sqrtf(pa), 1e-12f);
    float ix = (1.f + epsp[0]) / fmaxf(sqrtf(px), 1e-12f);
    float o[4];
    o[0] = a.x * ia + xv.x * ix;
    o[1] = a.y * ia + xv.y * ix;
    o[2] = a.z * ia + xv.z * ix;
    o[3] = a.w * ia + xv.w * ix;
    __nv_bfloat16 h[4], l[4];
    #pragma unroll
    for (int j = 0; j < 4; j++) {
        h[j] = __float2bfloat16(o[j]);
        l[j] = __float2bfloat16(o[j] - __bfloat162float(h[j]));
    }
    *(uint2*)(g_xhi + node * DD + lane * 4) = make_uint2(pack2bf(h[0], h[1]), pack2bf(h[2], h[3]));
    *(uint2*)(g_xlo + node * DD + lane * 4) = make_uint2(pack2bf(l[0], l[1]), pack2bf(l[2], l[3]));
}

// ---------------- shared GEMM machinery (validated R8-R15) ----------------
__device__ __forceinline__ void prefetch_w(char* sm, uint32_t woff, int mat, int ck) {
    int tid = threadIdx.x;
    const __nv_bfloat16* gh = g_whi + mat * 16384 + ck * 32;
    const __nv_bfloat16* gl = g_wlo + mat * 16384 + ck * 32;
    uint32_t sh = smem_u32(sm + woff);
    uint32_t sl = sh + PSW;
    for (int i = tid; i < 512; i += 256) {
        int row = i >> 2, q = i & 3;
        uint32_t so = (uint32_t)(row * PITCH + q * 8) * 2;
        cp16(sh + so, gh + row * 128 + q * 8);
        cp16(sl + so, gl + row * 128 + q * 8);
    }
}

// X chunk for 64-row tile: 64 rows x 32 cols, hi+lo planes
__device__ __forceinline__ void prefetch_x_guarded(char* sm, uint32_t xoff, int row0, int ck) {
    int tid = threadIdx.x;
    uint32_t sh = smem_u32(sm + xoff);
    {
        int i = tid;
        int row = i >> 2, q = i & 3;
        int gr = row0 + row;
        uint32_t so = (uint32_t)(row * PITCH + q * 8) * 2;
        if (gr < NN) {
            cp16(sh + so, g_xhi + gr * DD + ck * 32 + q * 8);
            cp16(sh + PSX + so, g_xlo + gr * DD + ck * 32 + q * 8);
        } else {
            uint4 z = make_uint4(0, 0, 0, 0);
            *(uint4*)(sm + xoff + so) = z;
            *(uint4*)(sm + xoff + PSX + so) = z;
        }
    }
}

// A loaded once, multiplied by both W planes (hi+lo); M=64 tile: mt<2
__device__ __forceinline__ void do_pass2(uint32_t abase, uint32_t bwh, uint32_t bwl,
                                         int wm, int wn, int lane, float acc[2][4][4]) {
    #pragma unroll
    for (int ks = 0; ks < 2; ks++) {
        uint32_t af[2][4];
        #pragma unroll
        for (int mt = 0; mt < 2; mt++) {
            int row = wm * 32 + mt * 16 + (lane & 7) + ((lane >> 3) & 1) * 8;
            int col = ks * 16 + ((lane >> 4) & 1) * 8;
            ldm_x4(abase + (row * PITCH + col) * 2, af[mt]);
        }
        uint32_t bh[4][2], bl[4][2];
        #pragma unroll
        for (int jp = 0; jp < 2; jp++) {
            int n = wn * 32 + jp * 16 + ((lane >> 4) & 1) * 8 + (lane & 7);
            int col = ks * 16 + ((lane >> 3) & 1) * 8;
            uint32_t r4[4];
            ldm_x4(bwh + (n * PITCH + col) * 2, r4);
            bh[jp * 2][0] = r4[0]; bh[jp * 2][1] = r4[1];
            bh[jp * 2 + 1][0] = r4[2]; bh[jp * 2 + 1][1] = r4[3];
            ldm_x4(bwl + (n * PITCH + col) * 2, r4);
            bl[jp * 2][0] = r4[0]; bl[jp * 2][1] = r4[1];
            bl[jp * 2 + 1][0] = r4[2]; bl[jp * 2 + 1][1] = r4[3];
        }
        #pragma unroll
        for (int mt = 0; mt < 2; mt++)
            #pragma unroll
            for (int nt = 0; nt < 4; nt++) {
                mma_bf16(acc[mt][nt], af[mt], bh[nt]);
                mma_bf16(acc[mt][nt], af[mt], bl[nt]);
            }
    }
}

// single pass: Xlo against W-hi
__device__ __forceinline__ void do_pass1(uint32_t abase, uint32_t bwh,
                                         int wm, int wn, int lane, float acc[2][4][4]) {
    #pragma unroll
    for (int ks = 0; ks < 2; ks++) {
        uint32_t af[2][4];
        #pragma unroll
        for (int mt = 0; mt < 2; mt++) {
            int row = wm * 32 + mt * 16 + (lane & 7) + ((lane >> 3) & 1) * 8;
            int col = ks * 16 + ((lane >> 4) & 1) * 8;
            ldm_x4(abase + (row * PITCH + col) * 2, af[mt]);
        }
        uint32_t bf[4][2];
        #pragma unroll
        for (int jp = 0; jp < 2; jp++) {
            int n = wn * 32 + jp * 16 + ((lane >> 4) & 1) * 8 + (lane & 7);
            int col = ks * 16 + ((lane >> 3) & 1) * 8;
            uint32_t r4[4];
            ldm_x4(bwh + (n * PITCH + col) * 2, r4);
            bf[jp * 2][0] = r4[0]; bf[jp * 2][1] = r4[1];
            bf[jp * 2 + 1][0] = r4[2]; bf[jp * 2 + 1][1] = r4[3];
        }
        #pragma unroll
        for (int mt = 0; mt < 2; mt++)
            #pragma unroll
            for (int nt = 0; nt < 4; nt++)
                mma_bf16(acc[mt][nt], af[mt], bf[nt]);
    }
}

extern __shared__ __align__(16) char dsm[];

// ---------------- GEMM1: h = comb @ W1 + b1 -> g_h, BN stats via atomics ----------------
__global__ void __launch_bounds__(256) k_gemm1_p(int mat, const float* __restrict__ b) {
    char* sm = dsm;
    int tid = threadIdx.x;
    int wid = tid >> 5, lane = tid & 31;
    int wm = wid & 1, wn = wid >> 1;
    int row0 = blockIdx.x * 64;

    float acc[2][4][4];
    #pragma unroll
    for (int mt = 0; mt < 2; mt++)
        #pragma unroll
        for (int nt = 0; nt < 4; nt++)
            #pragma unroll
            for (int i = 0; i < 4; i++) acc[mt][nt][i] = 0.f;

    prefetch_x_guarded(sm, X_OFF(0), row0, 0);
    prefetch_w(sm, W_OFF1(0), mat, 0);
    CP_COMMIT();

    int buf = 0;
    for (int ck = 0; ck < 4; ck++) {
        __syncthreads();
        if (ck < 3) {
            prefetch_x_guarded(sm, X_OFF(buf ^ 1), row0, ck + 1);
            prefetch_w(sm, W_OFF1(buf ^ 1), mat, ck + 1);
            CP_COMMIT();
            CP_WAIT(1);
        } else {
            CP_WAIT(0);
        }
        __syncthreads();
        uint32_t axh = smem_u32(sm + X_OFF(buf));
        uint32_t axl = axh + PSX;
        uint32_t bwh = smem_u32(sm + W_OFF1(buf));
        do_pass2(axh, bwh, bwh + PSW, wm, wn, lane, acc);  // Xhi*(Whi+Wlo)
        do_pass1(axl, bwh, wm, wn, lane, acc);             // Xlo*Whi
        buf ^= 1;
    }

    // epilogue: bias, store h, BN partials -> global atomics
    float ls[4][2], lq[4][2];
    #pragma unroll
    for (int nt = 0; nt < 4; nt++) { ls[nt][0] = ls[nt][1] = lq[nt][0] = lq[nt][1] = 0.f; }
    #pragma unroll
    for (int mt = 0; mt < 2; mt++) {
        int r0 = row0 + wm * 32 + mt * 16 + (lane >> 2);
        int r1 = r0 + 8;
        #pragma unroll
        for (int nt = 0; nt < 4; nt++) {
            int c = wn * 32 + nt * 8 + (lane & 3) * 2;
            float b0 = b[c], b1 = b[c + 1];
            float v0 = acc[mt][nt][0] + b0, v1 = acc[mt][nt][1] + b1;
            float v2 = acc[mt][nt][2] + b0, v3 = acc[mt][nt][3] + b1;
            if (r0 < NN) {
                *(float2*)(g_h + r0 * DD + c) = make_float2(v0, v1);
                ls[nt][0] += v0; ls[nt][1] += v1;
                lq[nt][0] += v0 * v0; lq[nt][1] += v1 * v1;
            }
            if (r1 < NN) {
                *(float2*)(g_h + r1 * DD + c) = make_float2(v2, v3);
                ls[nt][0] += v2; ls[nt][1] += v3;
                lq[nt][0] += v2 * v2; lq[nt][1] += v3 * v3;
            }
        }
    }
    #pragma unroll
    for (int off = 4; off <= 16; off <<= 1) {
        #pragma unroll
        for (int nt = 0; nt < 4; nt++) {
            ls[nt][0] += __shfl_xor_sync(0xffffffffu, ls[nt][0], off);
            ls[nt][1] += __shfl_xor_sync(0xffffffffu, ls[nt][1], off);
            lq[nt][0] += __shfl_xor_sync(0xffffffffu, lq[nt][0], off);
            lq[nt][1] += __shfl_xor_sync(0xffffffffu, lq[nt][1], off);
        }
    }
    __syncthreads();
    float* ssum = (float*)sm;
    float* ssq  = ssum + 256;
    if (lane < 4) {
        #pragma unroll
        for (int nt = 0; nt < 4; nt++) {
            ssum[wid * 32 + nt * 8 + lane * 2]     = ls[nt][0];
            ssum[wid * 32 + nt * 8 + lane * 2 + 1] = ls[nt][1];
            ssq[wid * 32 + nt * 8 + lane * 2]      = lq[nt][0];
            ssq[wid * 32 + nt * 8 + lane * 2 + 1]  = lq[nt][1];
        }
    }
    __syncthreads();
    if (tid < DD) {
        int w0 = (tid >> 5) * 2;
        float s = ssum[w0 * 32 + (tid & 31)] + ssum[(w0 + 1) * 32 + (tid & 31)];
        float q = ssq[w0 * 32 + (tid & 31)] + ssq[(w0 + 1) * 32 + (tid & 31)];
        atomicAdd(&g_sum[tid], s);
        atomicAdd(&g_sumsq[tid], q);
    }
}

// ---------------- GEMM2: out = relu?(bn_relu(h) @ W2 + b2); BN finalize inline ----------------
__global__ void __launch_bounds__(256) k_gemm2_p(int mat, const float* __restrict__ gamma,
                                                 const float* __restrict__ beta,
                                                 const float* __restrict__ b,
                                                 float* __restrict__ OutExt,
                                                 int internal, int do_relu) {
    char* sm = dsm;
    float* Out = internal ? (float*)g_x : OutExt;
    int tid = threadIdx.x;
    int wid = tid >> 5, lane = tid & 31;
    int wm = wid & 1, wn = wid >> 1;
    int row0 = blockIdx.x * 64;

    float acc[2][4][4];
    #pragma unroll
    for (int mt = 0; mt < 2; mt++)
        #pragma unroll
        for (int nt = 0; nt < 4; nt++)
            #pragma unroll
            for (int i = 0; i < 4; i++) acc[mt][nt][i] = 0.f;

    prefetch_w(sm, W_OFF2(0), mat, 0);
    CP_COMMIT();

    // inline BN finalize: scale/shift into smem (overlaps W prefetch)
    float* sscale = (float*)(sm + SC_OFF);
    float* sshift = sscale + DD;
    if (tid < DD) {
        float mean = g_sum[tid] * (1.f / NN);
        float var  = g_sumsq[tid] * (1.f / NN) - mean * mean;
        float sc = gamma[tid] * rsqrtf(var + 1e-5f);
        sscale[tid] = sc;
        sshift[tid] = beta[tid] - mean * sc;
    }

    ushortt* xhi = (ushortt*)sm;
    ushortt* xlo = (ushortt*)(sm + PSX);
    int buf = 0;
    for (int ck = 0; ck < 4; ck++) {
        __syncthreads();   // prev passes done; also publishes sscale/sshift at ck=0
        if (ck < 3) {
            prefetch_w(sm, W_OFF2(buf ^ 1), mat, ck + 1);
            CP_COMMIT();
        }
        // convert X chunk hi+lo: 64 rows x 32 cols, 4 threads/row x 8 cols
        {
            int r = tid >> 2, q = tid & 3;
            int gr = row0 + r;
            int gc = ck * 32 + q * 8;
            uint4 hv = make_uint4(0, 0, 0, 0), lv = make_uint4(0, 0, 0, 0);
            if (gr < NN) {
                const float* srcp = g_h + gr * DD + gc;
                uint32_t hp[4], lp[4];
                #pragma unroll
                for (int i = 0; i < 4; i++) {
                    float v0 = fmaxf(fmaf(srcp[2 * i], sscale[gc + 2 * i], sshift[gc + 2 * i]), 0.f);
                    float v1 = fmaxf(fmaf(srcp[2 * i + 1], sscale[gc + 2 * i + 1], sshift[gc + 2 * i + 1]), 0.f);
                    __nv_bfloat16 h0 = __float2bfloat16(v0), h1 = __float2bfloat16(v1);
                    __nv_bfloat16 l0 = __float2bfloat16(v0 - __bfloat162float(h0));
                    __nv_bfloat16 l1 = __float2bfloat16(v1 - __bfloat162float(h1));
                    hp[i] = pack2bf(h0, h1);
                    lp[i] = pack2bf(l0, l1);
                }
                hv = make_uint4(hp[0], hp[1], hp[2], hp[3]);
                lv = make_uint4(lp[0], lp[1], lp[2], lp[3]);
            }
            *(uint4*)(xhi + r * PITCH + q * 8) = hv;
            *(uint4*)(xlo + r * PITCH + q * 8) = lv;
        }
        if (ck < 3) CP_WAIT(1); else CP_WAIT(0);
        __syncthreads();
        uint32_t axh = smem_u32(xhi);
        uint32_t axl = smem_u32(xlo);
        uint32_t bwh = smem_u32(sm + W_OFF2(buf));
        do_pass2(axh, bwh, bwh + PSW, wm, wn, lane, acc);
        do_pass1(axl, bwh, wm, wn, lane, acc);
        buf ^= 1;
    }

    #pragma unroll
    for (int mt = 0; mt < 2; mt++) {
        int r0 = row0 + wm * 32 + mt * 16 + (lane >> 2);
        int r1 = r0 + 8;
        #pragma unroll
        for (int nt = 0; nt < 4; nt++) {
            int c = wn * 32 + nt * 8 + (lane & 3) * 2;
            float b0 = b[c], b1 = b[c + 1];
            float v0 = acc[mt][nt][0] + b0, v1 = acc[mt][nt][1] + b1;
            float v2 = acc[mt][nt][2] + b0, v3 = acc[mt][nt][3] + b1;
            if (do_relu) {
                v0 = fmaxf(v0, 0.f); v1 = fmaxf(v1, 0.f);
                v2 = fmaxf(v2, 0.f); v3 = fmaxf(v3, 0.f);
            }
            if (r0 < NN) *(float2*)(Out + r0 * DD + c) = make_float2(v0, v1);
            if (r1 < NN) *(float2*)(Out + r1 * DD + c) = make_float2(v2, v3);
        }
    }
}

extern "C" void kernel_launch(void* const* d_in, const int* in_sizes, int n_in,
                              void* d_out, int out_size) {
    (void)in_sizes; (void)n_in; (void)out_size;
    const float* x     = (const float*)d_in[0];
    const int*   ei    = (const int*)d_in[1];   // int32 (JAX x64 disabled)
    const float* W1    = (const float*)d_in[2];
    const float* b1    = (const float*)d_in[3];
    const float* gamma = (const float*)d_in[4];
    const float* beta  = (const float*)d_in[5];
    const float* W2    = (const float*)d_in[6];
    const float* b2    = (const float*)d_in[7];
    const float* eps   = (const float*)d_in[8];
    float* out = (float*)d_out;

    const int* src = ei;
    const int* dst = ei + EE;

    cudaFuncSetAttribute(k_gemm1_p, cudaFuncAttributeMaxDynamicSharedMemorySize, SM1_TOT);
    cudaFuncSetAttribute(k_gemm2_p, cudaFuncAttributeMaxDynamicSharedMemorySize, SM2_TOT);

    k_prep<<<6 + (NN + 255) / 256, 256>>>(W1, W2);
    k_hist<<<(EE + 255) / 256, 256>>>(dst);
    k_scan_part<<<SCB, 1024>>>();
    k_scan_top<<<1, 64>>>();
    k_scan_add<<<SCB, 1024>>>();
    k_fill<<<(EE + 255) / 256, 256>>>(src, dst);

    for (int l = 0; l < 3; l++) {
        int use_ext = (l == 0) ? 1 : 0;
        int internal = (l == 2) ? 0 : 1;
        k_gather<<<(NN * 32 + 255) / 256, 256>>>(x, use_ext, eps + l);
        k_gemm1_p<<<NBT, 256, SM1_TOT>>>(l, b1 + l * DD);
        k_gemm2_p<<<NBT, 256, SM2_TOT>>>(3 + l, gamma + l * DD, beta + l * DD,
                                         b2 + l * DD, out, internal, (l < 2) ? 1 : 0);
    }
}

// round 17
// speedup vs baseline: 1.5251x; 1.0013x over previous
#include <cuda_runtime.h>
#include <cuda_bf16.h>
#include <cstdint>

#define NN 50000
#define DD 128
#define EE 800000
#define NBT 782           // ceil(50000/64) GEMM row tiles (M=64)
#define SCB 49            // scan blocks: 49*1024 >= NN

typedef unsigned short ushortt;

// ---------------- scratch (device globals) ----------------
__device__ __align__(16) float g_h[NN * DD];
__device__ __align__(16) float g_x[NN * DD];
__device__ __align__(16) __nv_bfloat16 g_xhi[NN * DD];  // combined feat, bf16 hi plane
__device__ __align__(16) __nv_bfloat16 g_xlo[NN * DD];  // combined feat, bf16 lo plane
__device__ float g_sum[DD];
__device__ float g_sumsq[DD];
// CSR
__device__ int g_cnt[NN];
__device__ int g_row[NN + 1];
__device__ int g_cur[NN];
__device__ int g_adj[EE];
__device__ int g_bsum[SCB];
// W images, transposed to [n][k] row-major bf16, hi/lo split; 6 mats
__device__ __align__(16) __nv_bfloat16 g_whi[6 * 16384];
__device__ __align__(16) __nv_bfloat16 g_wlo[6 * 16384];

// ---------------- helpers ----------------
__device__ __forceinline__ uint32_t smem_u32(const void* p) {
    uint32_t a;
    asm("{ .reg .u64 t; cvta.to.shared.u64 t, %1; cvt.u32.u64 %0, t; }" : "=r"(a) : "l"(p));
    return a;
}
__device__ __forceinline__ uint32_t pack2bf(__nv_bfloat16 a, __nv_bfloat16 b) {
    return (uint32_t)__bfloat16_as_ushort(a) | ((uint32_t)__bfloat16_as_ushort(b) << 16);
}
__device__ __forceinline__ void ldm_x4(uint32_t addr, uint32_t* r) {
    asm volatile("ldmatrix.sync.aligned.m8n8.x4.shared.b16 {%0,%1,%2,%3}, [%4];"
        : "=r"(r[0]), "=r"(r[1]), "=r"(r[2]), "=r"(r[3]) : "r"(addr));
}
__device__ __forceinline__ void mma_bf16(float* d, const uint32_t* a, const uint32_t* b) {
    asm volatile("mma.sync.aligned.m16n8k16.row.col.f32.bf16.bf16.f32 "
        "{%0,%1,%2,%3}, {%4,%5,%6,%7}, {%8,%9}, {%0,%1,%2,%3};"
        : "+f"(d[0]), "+f"(d[1]), "+f"(d[2]), "+f"(d[3])
        : "r"(a[0]), "r"(a[1]), "r"(a[2]), "r"(a[3]), "r"(b[0]), "r"(b[1]));
}
__device__ __forceinline__ void cp16(uint32_t sm, const void* g) {
    asm volatile("cp.async.ca.shared.global [%0], [%1], 16;" :: "r"(sm), "l"(g));
}
#define CP_COMMIT() asm volatile("cp.async.commit_group;" ::: "memory")
#define CP_WAIT(n)  asm volatile("cp.async.wait_group %0;" :: "n"(n) : "memory")

#define PITCH 40                 // bf16 per smem plane row (80B: conflict-free ldmatrix)
#define PSW 10240                // W plane bytes: 128*PITCH*2
#define PSX 5120                 // X plane bytes: 64*PITCH*2  (M=64 tiles)
// GEMM1 smem: [Xhi|Xlo](buf0) [Xhi|Xlo](buf1) [Whi|Wlo](buf0) [Whi|Wlo](buf1)
#define X_OFF(b)  ((b) * 2 * PSX)
#define W_OFF1(b) (4 * PSX + (b) * 2 * PSW)
#define SM1_TOT   (4 * PSX + 4 * PSW)     // 61440
// GEMM2 smem: [Xhi|Xlo] [Whi|Wlo](buf0) [Whi|Wlo](buf1) [scale|shift]
#define W_OFF2(b) (2 * PSX + (b) * 2 * PSW)
#define SC_OFF    (2 * PSX + 4 * PSW)
#define SM2_TOT   (2 * PSX + 4 * PSW + 1024)  // 52224

// ---------------- setup: weight prep + zero cnt/cur ----------------
__global__ void __launch_bounds__(256) k_prep(const float* __restrict__ W1,
                                              const float* __restrict__ W2) {
    if (blockIdx.x < 6) {
        int m = blockIdx.x;
        const float* src = (m < 3) ? (W1 + m * 16384) : (W2 + (m - 3) * 16384);
        __nv_bfloat16* hi = g_whi + m * 16384;
        __nv_bfloat16* lo = g_wlo + m * 16384;
        for (int i = threadIdx.x; i < 16384; i += 256) {
            int k = i >> 7, n = i & 127;
            float v = src[i];
            __nv_bfloat16 h = __float2bfloat16(v);
            __nv_bfloat16 l = __float2bfloat16(v - __bfloat162float(h));
            hi[n * 128 + k] = h;
            lo[n * 128 + k] = l;
        }
    } else {
        int i = (blockIdx.x - 6) * 256 + threadIdx.x;
        if (i < NN) { g_cnt[i] = 0; g_cur[i] = 0; }
    }
}
__global__ void k_hist(const int* __restrict__ dst) {
    int e = blockIdx.x * blockDim.x + threadIdx.x;
    if (e < EE) atomicAdd(&g_cnt[dst[e]], 1);
}

// ---------------- parallel scan: part (local) + add (merged top-level) ----------------
__global__ void __launch_bounds__(1024) k_scan_part() {
    __shared__ int sm[1024];
    int t = threadIdx.x;
    int i = blockIdx.x * 1024 + t;
    int c = (i < NN) ? g_cnt[i] : 0;
    sm[t] = c;
    __syncthreads();
    #pragma unroll
    for (int off = 1; off < 1024; off <<= 1) {
        int v = (t >= off) ? sm[t - off] : 0;
        __syncthreads();
        sm[t] += v;
        __syncthreads();
    }
    if (i < NN) g_row[i] = sm[t] - c;   // local exclusive
    if (t == 1023) g_bsum[blockIdx.x] = sm[1023];
}
__global__ void __launch_bounds__(1024) k_scan_add() {
    __shared__ int soff;
    if (threadIdx.x == 0) {
        int s = 0;
        for (int j = 0; j < blockIdx.x; j++) s += g_bsum[j];
        soff = s;
        if (blockIdx.x == 0) g_row[NN] = EE;
    }
    __syncthreads();
    int i = blockIdx.x * 1024 + threadIdx.x;
    if (i < NN) g_row[i] += soff;
}

__global__ void k_fill(const int* __restrict__ src, const int* __restrict__ dst) {
    int e = blockIdx.x * blockDim.x + threadIdx.x;
    if (e >= EE) return;
    int d = dst[e];
    int pos = atomicAdd(&g_cur[d], 1);
    g_adj[g_row[d] + pos] = src[e];
}

// ---------------- gather + combine -> bf16 hi/lo planes; zeroes BN stats ----------------
__global__ void k_gather(const float* __restrict__ Xext, int use_ext,
                         const float* __restrict__ epsp) {
    if (blockIdx.x == 0 && threadIdx.x < DD) {
        g_sum[threadIdx.x] = 0.f;
        g_sumsq[threadIdx.x] = 0.f;
    }
    const float* X = use_ext ? Xext : (const float*)g_x;
    int gid = blockIdx.x * blockDim.x + threadIdx.x;
    int node = gid >> 5;
    if (node >= NN) return;
    int lane = gid & 31;
    int beg = g_row[node], end = g_row[node + 1];
    float4 a = make_float4(0.f, 0.f, 0.f, 0.f);
    #pragma unroll 4
    for (int i = beg; i < end; i++) {
        int s = g_adj[i];
        float4 v = ((const float4*)X)[s * 32 + lane];
        a.x += v.x; a.y += v.y; a.z += v.z; a.w += v.w;
    }
    float4 xv = ((const float4*)X)[node * 32 + lane];
    float pa = a.x * a.x + a.y * a.y + a.z * a.z + a.w * a.w;
    float px = xv.x * xv.x + xv.y * xv.y + xv.z * xv.z + xv.w * xv.w;
    #pragma unroll
    for (int off = 16; off; off >>= 1) {
        pa += __shfl_xor_sync(0xffffffffu, pa, off);
        px += __shfl_xor_sync(0xffffffffu, px, off);
    }
    float ia = 1.f / fmaxf(sqrtf(pa), 1e-12f);
    float ix = (1.f + epsp[0]) / fmaxf(sqrtf(px), 1e-12f);
    float o[4];
    o[0] = a.x * ia + xv.x * ix;
    o[1] = a.y * ia + xv.y * ix;
    o[2] = a.z * ia + xv.z * ix;
    o[3] = a.w * ia + xv.w * ix;
    __nv_bfloat16 h[4], l[4];
    #pragma unroll
    for (int j = 0; j < 4; j++) {
        h[j] = __float2bfloat16(o[j]);
        l[j] = __float2bfloat16(o[j] - __bfloat162float(h[j]));
    }
    *(uint2*)(g_xhi + node * DD + lane * 4) = make_uint2(pack2bf(h[0], h[1]), pack2bf(h[2], h[3]));
    *(uint2*)(g_xlo + node * DD + lane * 4) = make_uint2(pack2bf(l[0], l[1]), pack2bf(l[2], l[3]));
}

// ---------------- shared GEMM machinery (validated R8-R16) ----------------
__device__ __forceinline__ void prefetch_w(char* sm, uint32_t woff, int mat, int ck) {
    int tid = threadIdx.x;
    const __nv_bfloat16* gh = g_whi + mat * 16384 + ck * 32;
    const __nv_bfloat16* gl = g_wlo + mat * 16384 + ck * 32;
    uint32_t sh = smem_u32(sm + woff);
    uint32_t sl = sh + PSW;
    for (int i = tid; i < 512; i += 256) {
        int row = i >> 2, q = i & 3;
        uint32_t so = (uint32_t)(row * PITCH + q * 8) * 2;
        cp16(sh + so, gh + row * 128 + q * 8);
        cp16(sl + so, gl + row * 128 + q * 8);
    }
}

// X chunk for 64-row tile: 64 rows x 32 cols, hi+lo planes
__device__ __forceinline__ void prefetch_x_guarded(char* sm, uint32_t xoff, int row0, int ck) {
    int tid = threadIdx.x;
    uint32_t sh = smem_u32(sm + xoff);
    {
        int i = tid;
        int row = i >> 2, q = i & 3;
        int gr = row0 + row;
        uint32_t so = (uint32_t)(row * PITCH + q * 8) * 2;
        if (gr < NN) {
            cp16(sh + so, g_xhi + gr * DD + ck * 32 + q * 8);
            cp16(sh + PSX + so, g_xlo + gr * DD + ck * 32 + q * 8);
        } else {
            uint4 z = make_uint4(0, 0, 0, 0);
            *(uint4*)(sm + xoff + so) = z;
            *(uint4*)(sm + xoff + PSX + so) = z;
        }
    }
}

// A loaded once, multiplied by both W planes (hi+lo); M=64 tile: mt<2
__device__ __forceinline__ void do_pass2(uint32_t abase, uint32_t bwh, uint32_t bwl,
                                         int wm, int wn, int lane, float acc[2][4][4]) {
    #pragma unroll
    for (int ks = 0; ks < 2; ks++) {
        uint32_t af[2][4];
        #pragma unroll
        for (int mt = 0; mt < 2; mt++) {
            int row = wm * 32 + mt * 16 + (lane & 7) + ((lane >> 3) & 1) * 8;
            int col = ks * 16 + ((lane >> 4) & 1) * 8;
            ldm_x4(abase + (row * PITCH + col) * 2, af[mt]);
        }
        uint32_t bh[4][2], bl[4][2];
        #pragma unroll
        for (int jp = 0; jp < 2; jp++) {
            int n = wn * 32 + jp * 16 + ((lane >> 4) & 1) * 8 + (lane & 7);
            int col = ks * 16 + ((lane >> 3) & 1) * 8;
            uint32_t r4[4];
            ldm_x4(bwh + (n * PITCH + col) * 2, r4);
            bh[jp * 2][0] = r4[0]; bh[jp * 2][1] = r4[1];
            bh[jp * 2 + 1][0] = r4[2]; bh[jp * 2 + 1][1] = r4[3];
            ldm_x4(bwl + (n * PITCH + col) * 2, r4);
            bl[jp * 2][0] = r4[0]; bl[jp * 2][1] = r4[1];
            bl[jp * 2 + 1][0] = r4[2]; bl[jp * 2 + 1][1] = r4[3];
        }
        #pragma unroll
        for (int mt = 0; mt < 2; mt++)
            #pragma unroll
            for (int nt = 0; nt < 4; nt++) {
                mma_bf16(acc[mt][nt], af[mt], bh[nt]);
                mma_bf16(acc[mt][nt], af[mt], bl[nt]);
            }
    }
}

// single pass: Xlo against W-hi
__device__ __forceinline__ void do_pass1(uint32_t abase, uint32_t bwh,
                                         int wm, int wn, int lane, float acc[2][4][4]) {
    #pragma unroll
    for (int ks = 0; ks < 2; ks++) {
        uint32_t af[2][4];
        #pragma unroll
        for (int mt = 0; mt < 2; mt++) {
            int row = wm * 32 + mt * 16 + (lane & 7) + ((lane >> 3) & 1) * 8;
            int col = ks * 16 + ((lane >> 4) & 1) * 8;
            ldm_x4(abase + (row * PITCH + col) * 2, af[mt]);
        }
        uint32_t bf[4][2];
        #pragma unroll
        for (int jp = 0; jp < 2; jp++) {
            int n = wn * 32 + jp * 16 + ((lane >> 4) & 1) * 8 + (lane & 7);
            int col = ks * 16 + ((lane >> 3) & 1) * 8;
            uint32_t r4[4];
            ldm_x4(bwh + (n * PITCH + col) * 2, r4);
            bf[jp * 2][0] = r4[0]; bf[jp * 2][1] = r4[1];
            bf[jp * 2 + 1][0] = r4[2]; bf[jp * 2 + 1][1] = r4[3];
        }
        #pragma unroll
        for (int mt = 0; mt < 2; mt++)
            #pragma unroll
            for (int nt = 0; nt < 4; nt++)
                mma_bf16(acc[mt][nt], af[mt], bf[nt]);
    }
}

extern __shared__ __align__(16) char dsm[];

// ---------------- GEMM1: h = comb @ W1 + b1 -> g_h, BN stats via atomics ----------------
__global__ void __launch_bounds__(256) k_gemm1_p(int mat, const float* __restrict__ b) {
    char* sm = dsm;
    int tid = threadIdx.x;
    int wid = tid >> 5, lane = tid & 31;
    int wm = wid & 1, wn = wid >> 1;
    int row0 = blockIdx.x * 64;

    float acc[2][4][4];
    #pragma unroll
    for (int mt = 0; mt < 2; mt++)
        #pragma unroll
        for (int nt = 0; nt < 4; nt++)
            #pragma unroll
            for (int i = 0; i < 4; i++) acc[mt][nt][i] = 0.f;

    prefetch_x_guarded(sm, X_OFF(0), row0, 0);
    prefetch_w(sm, W_OFF1(0), mat, 0);
    CP_COMMIT();

    int buf = 0;
    for (int ck = 0; ck < 4; ck++) {
        __syncthreads();
        if (ck < 3) {
            prefetch_x_guarded(sm, X_OFF(buf ^ 1), row0, ck + 1);
            prefetch_w(sm, W_OFF1(buf ^ 1), mat, ck + 1);
            CP_COMMIT();
            CP_WAIT(1);
        } else {
            CP_WAIT(0);
        }
        __syncthreads();
        uint32_t axh = smem_u32(sm + X_OFF(buf));
        uint32_t axl = axh + PSX;
        uint32_t bwh = smem_u32(sm + W_OFF1(buf));
        do_pass2(axh, bwh, bwh + PSW, wm, wn, lane, acc);  // Xhi*(Whi+Wlo)
        do_pass1(axl, bwh, wm, wn, lane, acc);             // Xlo*Whi
        buf ^= 1;
    }

    // epilogue: bias, store h, BN partials -> global atomics
    float ls[4][2], lq[4][2];
    #pragma unroll
    for (int nt = 0; nt < 4; nt++) { ls[nt][0] = ls[nt][1] = lq[nt][0] = lq[nt][1] = 0.f; }
    #pragma unroll
    for (int mt = 0; mt < 2; mt++) {
        int r0 = row0 + wm * 32 + mt * 16 + (lane >> 2);
        int r1 = r0 + 8;
        #pragma unroll
        for (int nt = 0; nt < 4; nt++) {
            int c = wn * 32 + nt * 8 + (lane & 3) * 2;
            float b0 = b[c], b1 = b[c + 1];
            float v0 = acc[mt][nt][0] + b0, v1 = acc[mt][nt][1] + b1;
            float v2 = acc[mt][nt][2] + b0, v3 = acc[mt][nt][3] + b1;
            if (r0 < NN) {
                *(float2*)(g_h + r0 * DD + c) = make_float2(v0, v1);
                ls[nt][0] += v0; ls[nt][1] += v1;
                lq[nt][0] += v0 * v0; lq[nt][1] += v1 * v1;
            }
            if (r1 < NN) {
                *(float2*)(g_h + r1 * DD + c) = make_float2(v2, v3);
                ls[nt][0] += v2; ls[nt][1] += v3;
                lq[nt][0] += v2 * v2; lq[nt][1] += v3 * v3;
            }
        }
    }
    #pragma unroll
    for (int off = 4; off <= 16; off <<= 1) {
        #pragma unroll
        for (int nt = 0; nt < 4; nt++) {
            ls[nt][0] += __shfl_xor_sync(0xffffffffu, ls[nt][0], off);
            ls[nt][1] += __shfl_xor_sync(0xffffffffu, ls[nt][1], off);
            lq[nt][0] += __shfl_xor_sync(0xffffffffu, lq[nt][0], off);
            lq[nt][1] += __shfl_xor_sync(0xffffffffu, lq[nt][1], off);
        }
    }
    __syncthreads();
    float* ssum = (float*)sm;
    float* ssq  = ssum + 256;
    if (lane < 4) {
        #pragma unroll
        for (int nt = 0; nt < 4; nt++) {
            ssum[wid * 32 + nt * 8 + lane * 2]     = ls[nt][0];
            ssum[wid * 32 + nt * 8 + lane * 2 + 1] = ls[nt][1];
            ssq[wid * 32 + nt * 8 + lane * 2]      = lq[nt][0];
            ssq[wid * 32 + nt * 8 + lane * 2 + 1]  = lq[nt][1];
        }
    }
    __syncthreads();
    if (tid < DD) {
        int w0 = (tid >> 5) * 2;
        float s = ssum[w0 * 32 + (tid & 31)] + ssum[(w0 + 1) * 32 + (tid & 31)];
        float q = ssq[w0 * 32 + (tid & 31)] + ssq[(w0 + 1) * 32 + (tid & 31)];
        atomicAdd(&g_sum[tid], s);
        atomicAdd(&g_sumsq[tid], q);
    }
}

// ---------------- GEMM2: out = relu?(bn_relu(h) @ W2 + b2); BN finalize inline ----------------
__global__ void __launch_bounds__(256) k_gemm2_p(int mat, const float* __restrict__ gamma,
                                                 const float* __restrict__ beta,
                                                 const float* __restrict__ b,
                                                 float* __restrict__ OutExt,
                                                 int internal, int do_relu) {
    char* sm = dsm;
    float* Out = internal ? (float*)g_x : OutExt;
    int tid = threadIdx.x;
    int wid = tid >> 5, lane = tid & 31;
    int wm = wid & 1, wn = wid >> 1;
    int row0 = blockIdx.x * 64;

    float acc[2][4][4];
    #pragma unroll
    for (int mt = 0; mt < 2; mt++)
        #pragma unroll
        for (int nt = 0; nt < 4; nt++)
            #pragma unroll
            for (int i = 0; i < 4; i++) acc[mt][nt][i] = 0.f;

    prefetch_w(sm, W_OFF2(0), mat, 0);
    CP_COMMIT();

    // inline BN finalize: scale/shift into smem (overlaps W prefetch)
    float* sscale = (float*)(sm + SC_OFF);
    float* sshift = sscale + DD;
    if (tid < DD) {
        float mean = g_sum[tid] * (1.f / NN);
        float var  = g_sumsq[tid] * (1.f / NN) - mean * mean;
        float sc = gamma[tid] * rsqrtf(var + 1e-5f);
        sscale[tid] = sc;
        sshift[tid] = beta[tid] - mean * sc;
    }

    ushortt* xhi = (ushortt*)sm;
    ushortt* xlo = (ushortt*)(sm + PSX);
    int buf = 0;
    for (int ck = 0; ck < 4; ck++) {
        __syncthreads();   // prev passes done; also publishes sscale/sshift at ck=0
        if (ck < 3) {
            prefetch_w(sm, W_OFF2(buf ^ 1), mat, ck + 1);
            CP_COMMIT();
        }
        // convert X chunk hi+lo: 64 rows x 32 cols, 4 threads/row x 8 cols
        {
            int r = tid >> 2, q = tid & 3;
            int gr = row0 + r;
            int gc = ck * 32 + q * 8;
            uint4 hv = make_uint4(0, 0, 0, 0), lv = make_uint4(0, 0, 0, 0);
            if (gr < NN) {
                const float* srcp = g_h + gr * DD + gc;
                uint32_t hp[4], lp[4];
                #pragma unroll
                for (int i = 0; i < 4; i++) {
                    float v0 = fmaxf(fmaf(srcp[2 * i], sscale[gc + 2 * i], sshift[gc + 2 * i]), 0.f);
                    float v1 = fmaxf(fmaf(srcp[2 * i + 1], sscale[gc + 2 * i + 1], sshift[gc + 2 * i + 1]), 0.f);
                    __nv_bfloat16 h0 = __float2bfloat16(v0), h1 = __float2bfloat16(v1);
                    __nv_bfloat16 l0 = __float2bfloat16(v0 - __bfloat162float(h0));
                    __nv_bfloat16 l1 = __float2bfloat16(v1 - __bfloat162float(h1));
                    hp[i] = pack2bf(h0, h1);
                    lp[i] = pack2bf(l0, l1);
                }
                hv = make_uint4(hp[0], hp[1], hp[2], hp[3]);
                lv = make_uint4(lp[0], lp[1], lp[2], lp[3]);
            }
            *(uint4*)(xhi + r * PITCH + q * 8) = hv;
            *(uint4*)(xlo + r * PITCH + q * 8) = lv;
        }
        if (ck < 3) CP_WAIT(1); else CP_WAIT(0);
        __syncthreads();
        uint32_t axh = smem_u32(xhi);
        uint32_t axl = smem_u32(xlo);
        uint32_t bwh = smem_u32(sm + W_OFF2(buf));
        do_pass2(axh, bwh, bwh + PSW, wm, wn, lane, acc);
        do_pass1(axl, bwh, wm, wn, lane, acc);
        buf ^= 1;
    }

    #pragma unroll
    for (int mt = 0; mt < 2; mt++) {
        int r0 = row0 + wm * 32 + mt * 16 + (lane >> 2);
        int r1 = r0 + 8;
        #pragma unroll
        for (int nt = 0; nt < 4; nt++) {
            int c = wn * 32 + nt * 8 + (lane & 3) * 2;
            float b0 = b[c], b1 = b[c + 1];
            float v0 = acc[mt][nt][0] + b0, v1 = acc[mt][nt][1] + b1;
            float v2 = acc[mt][nt][2] + b0, v3 = acc[mt][nt][3] + b1;
            if (do_relu) {
                v0 = fmaxf(v0, 0.f); v1 = fmaxf(v1, 0.f);
                v2 = fmaxf(v2, 0.f); v3 = fmaxf(v3, 0.f);
            }
            if (r0 < NN) *(float2*)(Out + r0 * DD + c) = make_float2(v0, v1);
            if (r1 < NN) *(float2*)(Out + r1 * DD + c) = make_float2(v2, v3);
        }
    }
}

extern "C" void kernel_launch(void* const* d_in, const int* in_sizes, int n_in,
                              void* d_out, int out_size) {
    (void)in_sizes; (void)n_in; (void)out_size;
    const float* x     = (const float*)d_in[0];
    const int*   ei    = (const int*)d_in[1];   // int32 (JAX x64 disabled)
    const float* W1    = (const float*)d_in[2];
    const float* b1    = (const float*)d_in[3];
    const float* gamma = (const float*)d_in[4];
    const float* beta  = (const float*)d_in[5];
    const float* W2    = (const float*)d_in[6];
    const float* b2    = (const float*)d_in[7];
    const float* eps   = (const float*)d_in[8];
    float* out = (float*)d_out;

    const int* src = ei;
    const int* dst = ei + EE;

    cudaFuncSetAttribute(k_gemm1_p, cudaFuncAttributeMaxDynamicSharedMemorySize, SM1_TOT);
    cudaFuncSetAttribute(k_gemm2_p, cudaFuncAttributeMaxDynamicSharedMemorySize, SM2_TOT);

    k_prep<<<6 + (NN + 255) / 256, 256>>>(W1, W2);          // launch 0
    k_hist<<<(EE + 255) / 256, 256>>>(dst);                 // launch 1
    k_scan_part<<<SCB, 1024>>>();                           // launch 2
    k_scan_add<<<SCB, 1024>>>();                            // launch 3 (merged top)
    k_fill<<<(EE + 255) / 256, 256>>>(src, dst);            // launch 4

    for (int l = 0; l < 3; l++) {
        int use_ext = (l == 0) ? 1 : 0;
        int internal = (l == 2) ? 0 : 1;
        k_gather<<<(NN * 32 + 255) / 256, 256>>>(x, use_ext, eps + l);   // l=0: launch 5 (profiled)
        k_gemm1_p<<<NBT, 256, SM1_TOT>>>(l, b1 + l * DD);
        k_gemm2_p<<<NBT, 256, SM2_TOT>>>(3 + l, gamma + l * DD, beta + l * DD,
                                         b2 + l * DD, out, internal, (l < 2) ? 1 : 0);
    }
}